// round 8
// baseline (speedup 1.0000x reference)
#include <cuda_runtime.h>
#include <cuda_bf16.h>
#include <cuda_fp16.h>
#include <cstdint>

// Problem shapes
#define BB 32
#define LL 48
#define DD 768
#define TT 32
#define VV 30522
#define HH 768
#define NPAD 30592   // 478 * 64
#define MPROJ 1056   // 32*33
#define MPROJP 1152
#define MTXT 1536

#define OUT_TEXT_ELEMS ((long)BB * LL * VV)
#define OUT_IOU_ELEMS  ((long)BB * 3 * TT * (TT+1))
#define OUT_IOU_BASE   (OUT_TEXT_ELEMS)
#define OUT_MASK_BASE  (OUT_TEXT_ELEMS + OUT_IOU_ELEMS)

// mega-kernel block ranges (order = dependency order)
#define G1GRID 72     // gemm1 tiles (12 x 6)
#define PRGRID 162    // projection tiles (9 x 6 x 3)
#define TWGRID 5736   // w_t2 transpose tiles (478 x 12)
#define VOGRID 2868   // vocab tiles (12 x 239)
#define IOGRID 33792  // iou cells: 32 batches * 32 * 33

// Scratch (device globals; no allocations allowed)
__device__ int   g_ctr[4];
__device__ float g_proj[3L * MPROJP * HH];
__device__ __nv_bfloat16 g_Athi[(long)MTXT * DD],  g_Atlo[(long)MTXT * DD];
__device__ __nv_bfloat16 g_Achi[(long)MPROJ * DD], g_Aclo[(long)MPROJ * DD];
__device__ __half        g_H1hi[(long)MTXT * HH];
__device__ __nv_bfloat16 g_Bw1hi[(long)HH * DD],   g_Bw1lo[(long)HH * DD];
__device__ __nv_bfloat16 g_Bi1hi[3L * HH * DD],    g_Bi1lo[3L * HH * DD];
__device__ __half        g_Bw2hi[(long)NPAD * DD];

// ---------------------------------------------------------------------------
// helpers
// ---------------------------------------------------------------------------
__device__ __forceinline__ uint32_t smem_u32(const void* p) {
    uint32_t a;
    asm("{ .reg .u64 t; cvta.to.shared.u64 t, %1; cvt.u32.u64 %0, t; }" : "=r"(a) : "l"(p));
    return a;
}
__device__ __forceinline__ void cp_async16(uint32_t saddr, const void* gptr) {
    asm volatile("cp.async.cg.shared.global [%0], [%1], 16;" :: "r"(saddr), "l"(gptr));
}
__device__ __forceinline__ void cp_async16z(uint32_t saddr, const void* gptr, bool pred) {
    int sz = pred ? 16 : 0;
    asm volatile("cp.async.cg.shared.global [%0], [%1], 16, %2;"
                 :: "r"(saddr), "l"(gptr), "r"(sz));
}
#define CP_COMMIT()  asm volatile("cp.async.commit_group;" ::: "memory")
#define CP_WAIT2()   asm volatile("cp.async.wait_group 2;" ::: "memory")
#define CP_WAIT1()   asm volatile("cp.async.wait_group 1;" ::: "memory")
#define CP_WAIT0()   asm volatile("cp.async.wait_group 0;" ::: "memory")

#define SWZ(o) ((o) ^ (((o) >> 3) & 0x70))

__device__ __forceinline__ void ldsm_x4(uint32_t addr, uint32_t& r0, uint32_t& r1,
                                        uint32_t& r2, uint32_t& r3) {
    asm volatile("ldmatrix.sync.aligned.m8n8.x4.shared.b16 {%0,%1,%2,%3}, [%4];"
                 : "=r"(r0), "=r"(r1), "=r"(r2), "=r"(r3) : "r"(addr));
}
__device__ __forceinline__ void mma_bf16(float* d, const uint32_t* a, const uint32_t* b) {
    asm volatile(
        "mma.sync.aligned.m16n8k16.row.col.f32.bf16.bf16.f32 "
        "{%0,%1,%2,%3}, {%4,%5,%6,%7}, {%8,%9}, {%0,%1,%2,%3};"
        : "+f"(d[0]), "+f"(d[1]), "+f"(d[2]), "+f"(d[3])
        : "r"(a[0]), "r"(a[1]), "r"(a[2]), "r"(a[3]), "r"(b[0]), "r"(b[1]));
}
__device__ __forceinline__ void mma_f16(float* d, const uint32_t* a, const uint32_t* b) {
    asm volatile(
        "mma.sync.aligned.m16n8k16.row.col.f32.f16.f16.f32 "
        "{%0,%1,%2,%3}, {%4,%5,%6,%7}, {%8,%9}, {%0,%1,%2,%3};"
        : "+f"(d[0]), "+f"(d[1]), "+f"(d[2]), "+f"(d[3])
        : "r"(a[0]), "r"(a[1]), "r"(a[2]), "r"(a[3]), "r"(b[0]), "r"(b[1]));
}

// producer/consumer sync
__device__ __forceinline__ void signal_ctr(int* c) {
    __syncthreads();
    if (threadIdx.x == 0) { __threadfence(); atomicAdd(c, 1); }
}
__device__ __forceinline__ void wait_ctr(int* c, int target) {
    if (threadIdx.x == 0) {
        volatile int* vc = c;
        while (*vc < target) __nanosleep(64);
    }
    __syncthreads();
    __threadfence();
}
__device__ __forceinline__ void wait_ctr2(int* c0, int t0, int* c1, int t1) {
    if (threadIdx.x == 0) {
        volatile int* v0 = c0;
        volatile int* v1 = c1;
        while (*v0 < t0 || *v1 < t1) __nanosleep(64);
    }
    __syncthreads();
    __threadfence();
}

// ---------------------------------------------------------------------------
// bf16 3-pass mainloop (tile 128x128, K=768, 3-stage cp.async)
// ---------------------------------------------------------------------------
#define NCHUNK 36

__device__ __forceinline__ void mainloop_bf16(
    uint32_t sbase, int tid, int wid, int lane, int row0, int col0, int Mclip,
    const __nv_bfloat16* __restrict__ Ahi, const __nv_bfloat16* __restrict__ Alo,
    const __nv_bfloat16* __restrict__ Bhi, const __nv_bfloat16* __restrict__ Blo,
    float acc[4][4][4])
{
    const int wm = (wid & 1) * 64;
    const int wn = (wid >> 1) * 32;
    const int a_m  = lane & 15;
    const int a_kb = (lane >> 4) << 4;
    const int b_n  = (lane & 7) + ((lane >> 4) << 3);
    const int b_kb = ((lane >> 3) & 1) << 4;

#define LOAD_CHUNKB(KC)                                                         \
    {                                                                           \
        int pass = (KC) / 12;                                                   \
        int kk = ((KC) - pass * 12) * 64;                                       \
        const __nv_bfloat16* Ap = (pass == 1) ? Alo : Ahi;                      \
        const __nv_bfloat16* Bp = (pass == 2) ? Blo : Bhi;                      \
        uint32_t sA = sbase + ((KC) % 3) * 32768;                               \
        uint32_t sB = sA + 16384;                                               \
        _Pragma("unroll")                                                       \
        for (int i = 0; i < 4; i++) {                                           \
            int idx = tid + (i << 8);                                           \
            int m = idx >> 3, j = idx & 7;                                      \
            int grow = row0 + m;                                                \
            bool pa = grow < Mclip;                                             \
            cp_async16z(sA + SWZ(m * 128 + j * 16),                             \
                        Ap + (size_t)(pa ? grow : 0) * DD + kk + j * 8, pa);    \
            cp_async16(sB + SWZ(m * 128 + j * 16),                              \
                       Bp + (size_t)(col0 + m) * DD + kk + j * 8);              \
        }                                                                       \
        CP_COMMIT();                                                            \
    }

    LOAD_CHUNKB(0);
    LOAD_CHUNKB(1);
    LOAD_CHUNKB(2);

    for (int kc = 0; kc < NCHUNK; kc++) {
        if (kc < NCHUNK - 2)       { CP_WAIT2(); }
        else if (kc == NCHUNK - 2) { CP_WAIT1(); }
        else                       { CP_WAIT0(); }
        __syncthreads();
        const uint32_t sA = sbase + (kc % 3) * 32768;
        const uint32_t sB = sA + 16384;

#pragma unroll
        for (int k16 = 0; k16 < 4; k16++) {
            const int kb = k16 * 32;
            uint32_t a[4][4], b[2][4];
#pragma unroll
            for (int mf = 0; mf < 4; mf++)
                ldsm_x4(sA + SWZ((wm + mf * 16 + a_m) * 128 + kb + a_kb),
                        a[mf][0], a[mf][1], a[mf][2], a[mf][3]);
#pragma unroll
            for (int np = 0; np < 2; np++)
                ldsm_x4(sB + SWZ((wn + np * 16 + b_n) * 128 + kb + b_kb),
                        b[np][0], b[np][1], b[np][2], b[np][3]);
#pragma unroll
            for (int mf = 0; mf < 4; mf++) {
#pragma unroll
                for (int nf = 0; nf < 4; nf++) {
                    uint32_t bb[2] = { b[nf >> 1][(nf & 1) * 2],
                                       b[nf >> 1][(nf & 1) * 2 + 1] };
                    mma_bf16(acc[mf][nf], a[mf], bb);
                }
            }
        }
        __syncthreads();
        if (kc + 3 < NCHUNK) LOAD_CHUNKB(kc + 3);
    }
#undef LOAD_CHUNKB
}

// ---------------------------------------------------------------------------
// MEGA kernel
// ---------------------------------------------------------------------------
__global__ __launch_bounds__(256, 2) void megafat(
    const __nv_bfloat16* __restrict__ Athi, const __nv_bfloat16* __restrict__ Atlo,
    const __nv_bfloat16* __restrict__ Bw1hi, const __nv_bfloat16* __restrict__ Bw1lo,
    const float* __restrict__ b_t1, __half* __restrict__ H1hi,
    const __nv_bfloat16* __restrict__ Achi, const __nv_bfloat16* __restrict__ Aclo,
    const __nv_bfloat16* __restrict__ Bi1hi, const __nv_bfloat16* __restrict__ Bi1lo,
    const float* __restrict__ b_i1, float* __restrict__ proj,
    const float* __restrict__ w_t2, __half* __restrict__ Bw2,
    const float* __restrict__ b_t2, float* __restrict__ out,
    const float* __restrict__ w_i2, const float* __restrict__ b_i2)
{
    extern __shared__ char smem[];
    const uint32_t sbase = smem_u32(smem);
    const int tid  = threadIdx.x;
    const int wid  = tid >> 5;
    const int lane = tid & 31;
    const int em = lane >> 2;
    const int en = (lane & 3) * 2;
    const int bid = blockIdx.x;

    if (bid < G1GRID) {
        // ===================== GEMM1: h1 -> fp16 hi =====================
        const int row0 = (bid / 6) * 128;
        const int col0 = (bid % 6) * 128;
        float acc[4][4][4];
#pragma unroll
        for (int i = 0; i < 4; i++)
#pragma unroll
            for (int j = 0; j < 4; j++)
#pragma unroll
                for (int r = 0; r < 4; r++) acc[i][j][r] = 0.f;
        mainloop_bf16(sbase, tid, wid, lane, row0, col0, MTXT,
                      Athi, Atlo, Bw1hi, Bw1lo, acc);
        const int wm = (wid & 1) * 64;
        const int wn = (wid >> 1) * 32;
#pragma unroll
        for (int mf = 0; mf < 4; mf++) {
#pragma unroll
            for (int half = 0; half < 2; half++) {
                int gr = row0 + wm + mf * 16 + em + half * 8;
#pragma unroll
                for (int nf = 0; nf < 4; nf++) {
                    int gc = col0 + wn + nf * 8 + en;
                    float vx = fmaxf(acc[mf][nf][half * 2]     + __ldg(b_t1 + gc), 0.f);
                    float vy = fmaxf(acc[mf][nf][half * 2 + 1] + __ldg(b_t1 + gc + 1), 0.f);
                    __half2 h;
                    h.x = __float2half_rn(vx);
                    h.y = __float2half_rn(vy);
                    *(__half2*)(H1hi + (size_t)gr * HH + gc) = h;
                }
            }
        }
        signal_ctr(&g_ctr[0]);

    } else if (bid < G1GRID + PRGRID) {
        // ===================== projections =====================
        const int p = bid - G1GRID;
        const int col0 = (p % 6) * 128;
        const int row0 = ((p / 6) % 9) * 128;
        const int pz = p / 54;
        float acc[4][4][4];
#pragma unroll
        for (int i = 0; i < 4; i++)
#pragma unroll
            for (int j = 0; j < 4; j++)
#pragma unroll
                for (int r = 0; r < 4; r++) acc[i][j][r] = 0.f;
        mainloop_bf16(sbase, tid, wid, lane, row0, col0, MPROJ,
                      Achi, Aclo, Bi1hi + (long)pz * HH * DD,
                      Bi1lo + (long)pz * HH * DD, acc);
        float* Cf = proj + (long)pz * MPROJP * HH;
        const int wm = (wid & 1) * 64;
        const int wn = (wid >> 1) * 32;
        const bool bias_on = (pz == 0);
#pragma unroll
        for (int mf = 0; mf < 4; mf++) {
#pragma unroll
            for (int half = 0; half < 2; half++) {
                int gr = row0 + wm + mf * 16 + em + half * 8;
#pragma unroll
                for (int nf = 0; nf < 4; nf++) {
                    int gc = col0 + wn + nf * 8 + en;
                    float vx = acc[mf][nf][half * 2];
                    float vy = acc[mf][nf][half * 2 + 1];
                    if (bias_on) { vx += __ldg(b_i1 + gc); vy += __ldg(b_i1 + gc + 1); }
                    float2 v = { vx, vy };
                    *(float2*)(Cf + (size_t)gr * HH + gc) = v;
                }
            }
        }
        signal_ctr(&g_ctr[1]);

    } else if (bid < G1GRID + PRGRID + TWGRID) {
        // ============== w_t2 transpose: (768 x 30522) fp32 -> (NPAD x 768) fp16 ==============
        const int bt = bid - (G1GRID + PRGRID);
        const int n0 = (bt % 478) * 64;
        const int k0 = (bt / 478) * 64;
        float* tt = (float*)smem;  // [64][65]
#pragma unroll
        for (int i = 0; i < 16; i++) {
            int idx = tid + (i << 8);
            int ky = idx >> 6, nx = idx & 63;
            int n = n0 + nx;
            tt[ky * 65 + nx] = (n < VV) ? w_t2[(long)(k0 + ky) * VV + n] : 0.f;
        }
        __syncthreads();
#pragma unroll
        for (int i = 0; i < 16; i++) {
            int idx = tid + (i << 8);
            int ny = idx >> 6, kx = idx & 63;
            Bw2[(long)(n0 + ny) * DD + k0 + kx] = __float2half_rn(tt[kx * 65 + ny]);
        }
        signal_ctr(&g_ctr[2]);

    } else if (bid < G1GRID + PRGRID + TWGRID + VOGRID) {
        // ===================== vocab GEMM (fp16 1-term) =====================
        wait_ctr2(&g_ctr[0], G1GRID, &g_ctr[2], TWGRID);
        const int v = bid - (G1GRID + PRGRID + TWGRID);
        const int col0 = (v % 239) * 128;
        const int row0 = (v / 239) * 128;
        const int wm = (wid & 1) * 64;
        const int wn = (wid >> 1) * 32;
        const int a_m  = lane & 15;
        const int a_kb = (lane >> 4) << 4;
        const int b_n  = (lane & 7) + ((lane >> 4) << 3);
        const int b_kb = ((lane >> 3) & 1) << 4;

        float acc[4][4][4];
#pragma unroll
        for (int i = 0; i < 4; i++)
#pragma unroll
            for (int j = 0; j < 4; j++)
#pragma unroll
                for (int r = 0; r < 4; r++) acc[i][j][r] = 0.f;

#define VCHUNK 12
#define LOAD_CHUNKV(KC)                                                         \
    {                                                                           \
        int kk = (KC) * 64;                                                     \
        uint32_t st = sbase + ((KC) % 3) * 32768;                               \
        _Pragma("unroll")                                                       \
        for (int i = 0; i < 4; i++) {                                           \
            int idx = tid + (i << 8);                                           \
            int m = idx >> 3, j = idx & 7;                                      \
            uint32_t so = SWZ(m * 128 + j * 16);                                \
            cp_async16(st + so,                                                 \
                       H1hi + (size_t)(row0 + m) * DD + kk + j * 8);            \
            cp_async16(st + 16384 + so,                                         \
                       Bw2 + (size_t)(col0 + m) * DD + kk + j * 8);             \
        }                                                                       \
        CP_COMMIT();                                                            \
    }

        LOAD_CHUNKV(0);
        LOAD_CHUNKV(1);
        LOAD_CHUNKV(2);

        for (int kc = 0; kc < VCHUNK; kc++) {
            if (kc < VCHUNK - 2)       { CP_WAIT2(); }
            else if (kc == VCHUNK - 2) { CP_WAIT1(); }
            else                       { CP_WAIT0(); }
            __syncthreads();
            const uint32_t sA = sbase + (kc % 3) * 32768;
            const uint32_t sB = sA + 16384;

#pragma unroll
            for (int k16 = 0; k16 < 4; k16++) {
                const int kb = k16 * 32;
                uint32_t a[4][4], b[2][4];
#pragma unroll
                for (int mf = 0; mf < 4; mf++)
                    ldsm_x4(sA + SWZ((wm + mf * 16 + a_m) * 128 + kb + a_kb),
                            a[mf][0], a[mf][1], a[mf][2], a[mf][3]);
#pragma unroll
                for (int np = 0; np < 2; np++)
                    ldsm_x4(sB + SWZ((wn + np * 16 + b_n) * 128 + kb + b_kb),
                            b[np][0], b[np][1], b[np][2], b[np][3]);
#pragma unroll
                for (int mf = 0; mf < 4; mf++) {
#pragma unroll
                    for (int nf = 0; nf < 4; nf++) {
                        uint32_t bb[2] = { b[nf >> 1][(nf & 1) * 2],
                                           b[nf >> 1][(nf & 1) * 2 + 1] };
                        mma_f16(acc[mf][nf], a[mf], bb);
                    }
                }
            }
            __syncthreads();
            if (kc + 3 < VCHUNK) LOAD_CHUNKV(kc + 3);
        }
#undef LOAD_CHUNKV

#pragma unroll
        for (int mf = 0; mf < 4; mf++) {
#pragma unroll
            for (int half = 0; half < 2; half++) {
                int gr = row0 + wm + mf * 16 + em + half * 8;
                float* orow = out + (size_t)gr * VV;
#pragma unroll
                for (int nf = 0; nf < 4; nf++) {
                    int gc = col0 + wn + nf * 8 + en;
                    if (gc + 1 < VV) {
                        float2 v = { acc[mf][nf][half * 2]     + __ldg(b_t2 + gc),
                                     acc[mf][nf][half * 2 + 1] + __ldg(b_t2 + gc + 1) };
                        *(float2*)(orow + gc) = v;
                    } else if (gc < VV) {
                        orow[gc] = acc[mf][nf][half * 2] + __ldg(b_t2 + gc);
                    }
                }
            }
        }

    } else {
        // ===================== IoU combine + mask =====================
        wait_ctr(&g_ctr[1], PRGRID);
        const int idx = bid - (G1GRID + PRGRID + TWGRID + VOGRID);
        const int e = idx % 33;
        const int s = (idx / 33) % 32;
        const int b = idx / (33 * 32);    // 0..31 now that IOGRID = 33792
        const int c = (s + e) >> 1;
        const int t = tid;

        if (t == 200 && idx < 32 * 33) {
            int i = idx / 33, j = idx % 33;
            float v = 0.f;
            int hi = (i + 17 < 33) ? (i + 17) : 33;
            if (j >= i + 1 && j < hi) v = 1.f;
            if (i < 16 && (i & 1) == 0 && j >= 18 + i && ((j - 18 - i) & 1) == 0) v = 1.f;
            out[OUT_MASK_BASE + idx] = v;
        }

        float k0 = 0.f, k1 = 0.f, k2 = 0.f;
        if (t < 192) {
            const long CS = (long)MPROJP * HH;
            const float4* ps = (const float4*)(proj + (long)(b * 33 + s) * HH);
            const float4* pc = (const float4*)(proj + CS + (long)(b * 33 + c) * HH);
            const float4* pe = (const float4*)(proj + 2 * CS + (long)(b * 33 + e) * HH);
            const float4* wv = (const float4*)(w_i2) + t * 3;

            float4 a = ps[t], bb = pc[t], cc = pe[t];
            float v0 = fmaxf(a.x + bb.x + cc.x, 0.f);
            float v1 = fmaxf(a.y + bb.y + cc.y, 0.f);
            float v2 = fmaxf(a.z + bb.z + cc.z, 0.f);
            float v3 = fmaxf(a.w + bb.w + cc.w, 0.f);
            float4 w0 = wv[0], w1 = wv[1], w2v = wv[2];
            k0 = v0 * w0.x + v1 * w0.w + v2 * w1.z + v3 * w2v.y;
            k1 = v0 * w0.y + v1 * w1.x + v2 * w1.w + v3 * w2v.z;
            k2 = v0 * w0.z + v1 * w1.y + v2 * w2v.x + v3 * w2v.w;
#pragma unroll
            for (int off = 16; off; off >>= 1) {
                k0 += __shfl_xor_sync(0xFFFFFFFFu, k0, off);
                k1 += __shfl_xor_sync(0xFFFFFFFFu, k1, off);
                k2 += __shfl_xor_sync(0xFFFFFFFFu, k2, off);
            }
        }
        __shared__ float red[3][6];
        const int w = t >> 5;
        if (t < 192 && lane == 0) { red[0][w] = k0; red[1][w] = k1; red[2][w] = k2; }
        __syncthreads();
        if (t == 0) {
            float r0 = __ldg(b_i2 + 0), r1 = __ldg(b_i2 + 1), r2 = __ldg(b_i2 + 2);
#pragma unroll
            for (int i = 0; i < 6; i++) { r0 += red[0][i]; r1 += red[1][i]; r2 += red[2][i]; }
            long base = OUT_IOU_BASE + ((long)b * 3) * (32 * 33) + (long)s * 33 + e;
            out[base + 0 * 32 * 33] = r0;
            out[base + 1 * 32 * 33] = r1;
            out[base + 2 * 32 * 33] = r2;
        }
    }
}

// ---------------------------------------------------------------------------
// prep 1: fp32 -> bf16 hi/lo splits of ht, hc + counter reset
// ---------------------------------------------------------------------------
__global__ void split_both_k(
    const float* __restrict__ in1, __nv_bfloat16* __restrict__ hi1, __nv_bfloat16* __restrict__ lo1, long n1,
    const float* __restrict__ in2, __nv_bfloat16* __restrict__ hi2, __nv_bfloat16* __restrict__ lo2, long n2)
{
    if (blockIdx.x == 0 && threadIdx.x == 0) {
        g_ctr[0] = 0; g_ctr[1] = 0; g_ctr[2] = 0; g_ctr[3] = 0;
    }
    long i = (long)blockIdx.x * blockDim.x + threadIdx.x;
    const float* in; __nv_bfloat16 *hi, *lo;
    if (i < n1) { in = in1; hi = hi1; lo = lo1; }
    else if (i < n1 + n2) { i -= n1; in = in2; hi = hi2; lo = lo2; }
    else return;
    float x = in[i];
    __nv_bfloat16 h = __float2bfloat16(x);
    hi[i] = h;
    lo[i] = __float2bfloat16(x - __bfloat162float(h));
}

// ---------------------------------------------------------------------------
// prep 2: transpose + split (bf16 hi/lo): z=0 -> w_t1, z=1..3 -> w_i1 chunks
// ---------------------------------------------------------------------------
__global__ void tsplit_w_k(const float* __restrict__ w1,
                           const float* __restrict__ wi1,
                           __nv_bfloat16* __restrict__ hi1, __nv_bfloat16* __restrict__ lo1,
                           __nv_bfloat16* __restrict__ hi2, __nv_bfloat16* __restrict__ lo2)
{
    const float* in; __nv_bfloat16 *hi, *lo;
    int z = blockIdx.z;
    if (z == 0) { in = w1; hi = hi1; lo = lo1; }
    else {
        in = wi1 + (long)(z - 1) * DD * HH;
        hi = hi2 + (long)(z - 1) * HH * DD;
        lo = lo2 + (long)(z - 1) * HH * DD;
    }
    __shared__ float t[32][33];
    int n0 = blockIdx.x * 32, k0 = blockIdx.y * 32;
    int n = n0 + threadIdx.x, k = k0 + threadIdx.y;
    t[threadIdx.y][threadIdx.x] = in[(long)k * HH + n];
    __syncthreads();
    int orow = n0 + threadIdx.y, ocol = k0 + threadIdx.x;
    float x = t[threadIdx.x][threadIdx.y];
    __nv_bfloat16 h = __float2bfloat16(x);
    hi[(long)orow * DD + ocol] = h;
    lo[(long)orow * DD + ocol] = __float2bfloat16(x - __bfloat162float(h));
}

// ---------------------------------------------------------------------------
extern "C" void kernel_launch(void* const* d_in, const int* in_sizes, int n_in,
                              void* d_out, int out_size)
{
    const float* ht   = (const float*)d_in[0];
    const float* hc   = (const float*)d_in[1];
    const float* w_t1 = (const float*)d_in[2];
    const float* b_t1 = (const float*)d_in[3];
    const float* w_t2 = (const float*)d_in[4];
    const float* b_t2 = (const float*)d_in[5];
    const float* w_i1 = (const float*)d_in[6];
    const float* b_i1 = (const float*)d_in[7];
    const float* w_i2 = (const float*)d_in[8];
    const float* b_i2 = (const float*)d_in[9];
    float* out = (float*)d_out;

    float* proj; cudaGetSymbolAddress((void**)&proj, g_proj);
    __nv_bfloat16 *Athi, *Atlo, *Achi, *Aclo;
    __nv_bfloat16 *Bw1hi, *Bw1lo, *Bi1hi, *Bi1lo;
    __half *H1hi, *Bw2hi;
    cudaGetSymbolAddress((void**)&Athi, g_Athi);
    cudaGetSymbolAddress((void**)&Atlo, g_Atlo);
    cudaGetSymbolAddress((void**)&Achi, g_Achi);
    cudaGetSymbolAddress((void**)&Aclo, g_Aclo);
    cudaGetSymbolAddress((void**)&H1hi, g_H1hi);
    cudaGetSymbolAddress((void**)&Bw1hi, g_Bw1hi);
    cudaGetSymbolAddress((void**)&Bw1lo, g_Bw1lo);
    cudaGetSymbolAddress((void**)&Bi1hi, g_Bi1hi);
    cudaGetSymbolAddress((void**)&Bi1lo, g_Bi1lo);
    cudaGetSymbolAddress((void**)&Bw2hi, g_Bw2hi);

    cudaFuncSetAttribute(megafat, cudaFuncAttributeMaxDynamicSharedMemorySize, 98304);

    // prep 1: splits of ht and hc (+ counter reset)
    {
        long n1 = (long)MTXT * DD, n2 = (long)MPROJ * DD;
        split_both_k<<<(int)((n1 + n2 + 255) / 256), 256>>>(
            ht, Athi, Atlo, n1, hc, Achi, Aclo, n2);
    }
    // prep 2: transpose+split w_t1 and w_i1
    tsplit_w_k<<<dim3(24, 24, 4), dim3(32, 32)>>>(w_t1, w_i1, Bw1hi, Bw1lo, Bi1hi, Bi1lo);
    // mega kernel: gemm1 + projections + w_t2 transpose + vocab + iou + mask
    megafat<<<G1GRID + PRGRID + TWGRID + VOGRID + IOGRID, 256, 98304>>>(
        Athi, Atlo, Bw1hi, Bw1lo, b_t1, H1hi,
        Achi, Aclo, Bi1hi, Bi1lo, b_i1, proj,
        w_t2, Bw2hi,
        b_t2, out,
        w_i2, b_i2);
}

// round 9
// speedup vs baseline: 1.4539x; 1.4539x over previous
#include <cuda_runtime.h>
#include <cuda_bf16.h>
#include <cuda_fp16.h>
#include <cstdint>

// Problem shapes
#define BB 32
#define LL 48
#define DD 768
#define TT 32
#define VV 30522
#define HH 768
#define NPAD 30592   // 239 * 128
#define MPROJ 1056   // 32*33
#define MPROJP 1152
#define MTXT 1536

#define OUT_TEXT_ELEMS ((long)BB * LL * VV)
#define OUT_IOU_ELEMS  ((long)BB * 3 * TT * (TT+1))
#define OUT_IOU_BASE   (OUT_TEXT_ELEMS)
#define OUT_MASK_BASE  (OUT_TEXT_ELEMS + OUT_IOU_ELEMS)

// mega-kernel block ranges (GEMM phases only)
#define G1GRID 72    // gemm1 tiles (12 x 6)
#define PRGRID 162   // projection tiles (9 x 6 x 3)
#define VOGRID 2868  // vocab tiles (12 x 239)

// Scratch (device globals; no allocations allowed)
__device__ int   g_ctr[2];
__device__ float g_proj[3L * MPROJP * HH];
__device__ __nv_bfloat16 g_Athi[(long)MTXT * DD],  g_Atlo[(long)MTXT * DD];
__device__ __nv_bfloat16 g_Achi[(long)MPROJ * DD], g_Aclo[(long)MPROJ * DD];
__device__ __half        g_H1hi[(long)MTXT * HH];
__device__ __nv_bfloat16 g_Bw1hi[(long)HH * DD],   g_Bw1lo[(long)HH * DD];
__device__ __nv_bfloat16 g_Bi1hi[3L * HH * DD],    g_Bi1lo[3L * HH * DD];
__device__ __half        g_Bw2hi[(long)NPAD * DD];

// ---------------------------------------------------------------------------
// helpers
// ---------------------------------------------------------------------------
__device__ __forceinline__ uint32_t smem_u32(const void* p) {
    uint32_t a;
    asm("{ .reg .u64 t; cvta.to.shared.u64 t, %1; cvt.u32.u64 %0, t; }" : "=r"(a) : "l"(p));
    return a;
}
__device__ __forceinline__ void cp_async16(uint32_t saddr, const void* gptr) {
    asm volatile("cp.async.cg.shared.global [%0], [%1], 16;" :: "r"(saddr), "l"(gptr));
}
__device__ __forceinline__ void cp_async16z(uint32_t saddr, const void* gptr, bool pred) {
    int sz = pred ? 16 : 0;
    asm volatile("cp.async.cg.shared.global [%0], [%1], 16, %2;"
                 :: "r"(saddr), "l"(gptr), "r"(sz));
}
#define CP_COMMIT()  asm volatile("cp.async.commit_group;" ::: "memory")
#define CP_WAIT2()   asm volatile("cp.async.wait_group 2;" ::: "memory")
#define CP_WAIT1()   asm volatile("cp.async.wait_group 1;" ::: "memory")
#define CP_WAIT0()   asm volatile("cp.async.wait_group 0;" ::: "memory")

#define SWZ(o) ((o) ^ (((o) >> 3) & 0x70))

__device__ __forceinline__ void ldsm_x4(uint32_t addr, uint32_t& r0, uint32_t& r1,
                                        uint32_t& r2, uint32_t& r3) {
    asm volatile("ldmatrix.sync.aligned.m8n8.x4.shared.b16 {%0,%1,%2,%3}, [%4];"
                 : "=r"(r0), "=r"(r1), "=r"(r2), "=r"(r3) : "r"(addr));
}
__device__ __forceinline__ void mma_bf16(float* d, const uint32_t* a, const uint32_t* b) {
    asm volatile(
        "mma.sync.aligned.m16n8k16.row.col.f32.bf16.bf16.f32 "
        "{%0,%1,%2,%3}, {%4,%5,%6,%7}, {%8,%9}, {%0,%1,%2,%3};"
        : "+f"(d[0]), "+f"(d[1]), "+f"(d[2]), "+f"(d[3])
        : "r"(a[0]), "r"(a[1]), "r"(a[2]), "r"(a[3]), "r"(b[0]), "r"(b[1]));
}
__device__ __forceinline__ void mma_f16(float* d, const uint32_t* a, const uint32_t* b) {
    asm volatile(
        "mma.sync.aligned.m16n8k16.row.col.f32.f16.f16.f32 "
        "{%0,%1,%2,%3}, {%4,%5,%6,%7}, {%8,%9}, {%0,%1,%2,%3};"
        : "+f"(d[0]), "+f"(d[1]), "+f"(d[2]), "+f"(d[3])
        : "r"(a[0]), "r"(a[1]), "r"(a[2]), "r"(a[3]), "r"(b[0]), "r"(b[1]));
}

// producer/consumer sync
__device__ __forceinline__ void signal_ctr(int* c) {
    __syncthreads();
    if (threadIdx.x == 0) { __threadfence(); atomicAdd(c, 1); }
}
__device__ __forceinline__ void wait_ctr(int* c, int target) {
    if (threadIdx.x == 0) {
        volatile int* vc = c;
        while (*vc < target) __nanosleep(64);
    }
    __syncthreads();
    __threadfence();
}

// ---------------------------------------------------------------------------
// bf16 3-pass mainloop (tile 128x128, K=768, 3-stage cp.async)
// ---------------------------------------------------------------------------
#define NCHUNK 36

__device__ __forceinline__ void mainloop_bf16(
    uint32_t sbase, int tid, int wid, int lane, int row0, int col0, int Mclip,
    const __nv_bfloat16* __restrict__ Ahi, const __nv_bfloat16* __restrict__ Alo,
    const __nv_bfloat16* __restrict__ Bhi, const __nv_bfloat16* __restrict__ Blo,
    float acc[4][4][4])
{
    const int wm = (wid & 1) * 64;
    const int wn = (wid >> 1) * 32;
    const int a_m  = lane & 15;
    const int a_kb = (lane >> 4) << 4;
    const int b_n  = (lane & 7) + ((lane >> 4) << 3);
    const int b_kb = ((lane >> 3) & 1) << 4;

#define LOAD_CHUNKB(KC)                                                         \
    {                                                                           \
        int pass = (KC) / 12;                                                   \
        int kk = ((KC) - pass * 12) * 64;                                       \
        const __nv_bfloat16* Ap = (pass == 1) ? Alo : Ahi;                      \
        const __nv_bfloat16* Bp = (pass == 2) ? Blo : Bhi;                      \
        uint32_t sA = sbase + ((KC) % 3) * 32768;                               \
        uint32_t sB = sA + 16384;                                               \
        _Pragma("unroll")                                                       \
        for (int i = 0; i < 4; i++) {                                           \
            int idx = tid + (i << 8);                                           \
            int m = idx >> 3, j = idx & 7;                                      \
            int grow = row0 + m;                                                \
            bool pa = grow < Mclip;                                             \
            cp_async16z(sA + SWZ(m * 128 + j * 16),                             \
                        Ap + (size_t)(pa ? grow : 0) * DD + kk + j * 8, pa);    \
            cp_async16(sB + SWZ(m * 128 + j * 16),                              \
                       Bp + (size_t)(col0 + m) * DD + kk + j * 8);              \
        }                                                                       \
        CP_COMMIT();                                                            \
    }

    LOAD_CHUNKB(0);
    LOAD_CHUNKB(1);
    LOAD_CHUNKB(2);

    for (int kc = 0; kc < NCHUNK; kc++) {
        if (kc < NCHUNK - 2)       { CP_WAIT2(); }
        else if (kc == NCHUNK - 2) { CP_WAIT1(); }
        else                       { CP_WAIT0(); }
        __syncthreads();
        const uint32_t sA = sbase + (kc % 3) * 32768;
        const uint32_t sB = sA + 16384;

#pragma unroll
        for (int k16 = 0; k16 < 4; k16++) {
            const int kb = k16 * 32;
            uint32_t a[4][4], b[2][4];
#pragma unroll
            for (int mf = 0; mf < 4; mf++)
                ldsm_x4(sA + SWZ((wm + mf * 16 + a_m) * 128 + kb + a_kb),
                        a[mf][0], a[mf][1], a[mf][2], a[mf][3]);
#pragma unroll
            for (int np = 0; np < 2; np++)
                ldsm_x4(sB + SWZ((wn + np * 16 + b_n) * 128 + kb + b_kb),
                        b[np][0], b[np][1], b[np][2], b[np][3]);
#pragma unroll
            for (int mf = 0; mf < 4; mf++) {
#pragma unroll
                for (int nf = 0; nf < 4; nf++) {
                    uint32_t bb[2] = { b[nf >> 1][(nf & 1) * 2],
                                       b[nf >> 1][(nf & 1) * 2 + 1] };
                    mma_bf16(acc[mf][nf], a[mf], bb);
                }
            }
        }
        __syncthreads();
        if (kc + 3 < NCHUNK) LOAD_CHUNKB(kc + 3);
    }
#undef LOAD_CHUNKB
}

// ---------------------------------------------------------------------------
// GEMM mega kernel: gemm1 (72) -> proj (162) -> vocab (2868, waits on gemm1)
// ---------------------------------------------------------------------------
__global__ __launch_bounds__(256, 2) void mega_gemm(
    const __nv_bfloat16* __restrict__ Athi, const __nv_bfloat16* __restrict__ Atlo,
    const __nv_bfloat16* __restrict__ Bw1hi, const __nv_bfloat16* __restrict__ Bw1lo,
    const float* __restrict__ b_t1, __half* __restrict__ H1hi,
    const __nv_bfloat16* __restrict__ Achi, const __nv_bfloat16* __restrict__ Aclo,
    const __nv_bfloat16* __restrict__ Bi1hi, const __nv_bfloat16* __restrict__ Bi1lo,
    const float* __restrict__ b_i1, float* __restrict__ proj,
    const __half* __restrict__ Bw2,
    const float* __restrict__ b_t2, float* __restrict__ out)
{
    extern __shared__ char smem[];
    const uint32_t sbase = smem_u32(smem);
    const int tid  = threadIdx.x;
    const int wid  = tid >> 5;
    const int lane = tid & 31;
    const int em = lane >> 2;
    const int en = (lane & 3) * 2;
    const int bid = blockIdx.x;

    if (bid < G1GRID) {
        // ===================== GEMM1: h1 -> fp16 hi =====================
        const int row0 = (bid / 6) * 128;
        const int col0 = (bid % 6) * 128;
        float acc[4][4][4];
#pragma unroll
        for (int i = 0; i < 4; i++)
#pragma unroll
            for (int j = 0; j < 4; j++)
#pragma unroll
                for (int r = 0; r < 4; r++) acc[i][j][r] = 0.f;
        mainloop_bf16(sbase, tid, wid, lane, row0, col0, MTXT,
                      Athi, Atlo, Bw1hi, Bw1lo, acc);
        const int wm = (wid & 1) * 64;
        const int wn = (wid >> 1) * 32;
#pragma unroll
        for (int mf = 0; mf < 4; mf++) {
#pragma unroll
            for (int half = 0; half < 2; half++) {
                int gr = row0 + wm + mf * 16 + em + half * 8;
#pragma unroll
                for (int nf = 0; nf < 4; nf++) {
                    int gc = col0 + wn + nf * 8 + en;
                    float vx = fmaxf(acc[mf][nf][half * 2]     + __ldg(b_t1 + gc), 0.f);
                    float vy = fmaxf(acc[mf][nf][half * 2 + 1] + __ldg(b_t1 + gc + 1), 0.f);
                    __half2 h;
                    h.x = __float2half_rn(vx);
                    h.y = __float2half_rn(vy);
                    *(__half2*)(H1hi + (size_t)gr * HH + gc) = h;
                }
            }
        }
        signal_ctr(&g_ctr[0]);

    } else if (bid < G1GRID + PRGRID) {
        // ===================== projections =====================
        const int p = bid - G1GRID;
        const int col0 = (p % 6) * 128;
        const int row0 = ((p / 6) % 9) * 128;
        const int pz = p / 54;
        float acc[4][4][4];
#pragma unroll
        for (int i = 0; i < 4; i++)
#pragma unroll
            for (int j = 0; j < 4; j++)
#pragma unroll
                for (int r = 0; r < 4; r++) acc[i][j][r] = 0.f;
        mainloop_bf16(sbase, tid, wid, lane, row0, col0, MPROJ,
                      Achi, Aclo, Bi1hi + (long)pz * HH * DD,
                      Bi1lo + (long)pz * HH * DD, acc);
        float* Cf = proj + (long)pz * MPROJP * HH;
        const int wm = (wid & 1) * 64;
        const int wn = (wid >> 1) * 32;
        const bool bias_on = (pz == 0);
#pragma unroll
        for (int mf = 0; mf < 4; mf++) {
#pragma unroll
            for (int half = 0; half < 2; half++) {
                int gr = row0 + wm + mf * 16 + em + half * 8;
#pragma unroll
                for (int nf = 0; nf < 4; nf++) {
                    int gc = col0 + wn + nf * 8 + en;
                    float vx = acc[mf][nf][half * 2];
                    float vy = acc[mf][nf][half * 2 + 1];
                    if (bias_on) { vx += __ldg(b_i1 + gc); vy += __ldg(b_i1 + gc + 1); }
                    float2 v = { vx, vy };
                    *(float2*)(Cf + (size_t)gr * HH + gc) = v;
                }
            }
        }

    } else {
        // ===================== vocab GEMM (fp16 1-term) =====================
        wait_ctr(&g_ctr[0], G1GRID);
        const int v = bid - (G1GRID + PRGRID);
        const int col0 = (v % 239) * 128;
        const int row0 = (v / 239) * 128;
        const int wm = (wid & 1) * 64;
        const int wn = (wid >> 1) * 32;
        const int a_m  = lane & 15;
        const int a_kb = (lane >> 4) << 4;
        const int b_n  = (lane & 7) + ((lane >> 4) << 3);
        const int b_kb = ((lane >> 3) & 1) << 4;

        float acc[4][4][4];
#pragma unroll
        for (int i = 0; i < 4; i++)
#pragma unroll
            for (int j = 0; j < 4; j++)
#pragma unroll
                for (int r = 0; r < 4; r++) acc[i][j][r] = 0.f;

#define VCHUNK 12
#define LOAD_CHUNKV(KC)                                                         \
    {                                                                           \
        int kk = (KC) * 64;                                                     \
        uint32_t st = sbase + ((KC) % 3) * 32768;                               \
        _Pragma("unroll")                                                       \
        for (int i = 0; i < 4; i++) {                                           \
            int idx = tid + (i << 8);                                           \
            int m = idx >> 3, j = idx & 7;                                      \
            uint32_t so = SWZ(m * 128 + j * 16);                                \
            cp_async16(st + so,                                                 \
                       H1hi + (size_t)(row0 + m) * DD + kk + j * 8);            \
            cp_async16(st + 16384 + so,                                         \
                       Bw2 + (size_t)(col0 + m) * DD + kk + j * 8);             \
        }                                                                       \
        CP_COMMIT();                                                            \
    }

        LOAD_CHUNKV(0);
        LOAD_CHUNKV(1);
        LOAD_CHUNKV(2);

        for (int kc = 0; kc < VCHUNK; kc++) {
            if (kc < VCHUNK - 2)       { CP_WAIT2(); }
            else if (kc == VCHUNK - 2) { CP_WAIT1(); }
            else                       { CP_WAIT0(); }
            __syncthreads();
            const uint32_t sA = sbase + (kc % 3) * 32768;
            const uint32_t sB = sA + 16384;

#pragma unroll
            for (int k16 = 0; k16 < 4; k16++) {
                const int kb = k16 * 32;
                uint32_t a[4][4], b[2][4];
#pragma unroll
                for (int mf = 0; mf < 4; mf++)
                    ldsm_x4(sA + SWZ((wm + mf * 16 + a_m) * 128 + kb + a_kb),
                            a[mf][0], a[mf][1], a[mf][2], a[mf][3]);
#pragma unroll
                for (int np = 0; np < 2; np++)
                    ldsm_x4(sB + SWZ((wn + np * 16 + b_n) * 128 + kb + b_kb),
                            b[np][0], b[np][1], b[np][2], b[np][3]);
#pragma unroll
                for (int mf = 0; mf < 4; mf++) {
#pragma unroll
                    for (int nf = 0; nf < 4; nf++) {
                        uint32_t bb[2] = { b[nf >> 1][(nf & 1) * 2],
                                           b[nf >> 1][(nf & 1) * 2 + 1] };
                        mma_f16(acc[mf][nf], a[mf], bb);
                    }
                }
            }
            __syncthreads();
            if (kc + 3 < VCHUNK) LOAD_CHUNKV(kc + 3);
        }
#undef LOAD_CHUNKV

#pragma unroll
        for (int mf = 0; mf < 4; mf++) {
#pragma unroll
            for (int half = 0; half < 2; half++) {
                int gr = row0 + wm + mf * 16 + em + half * 8;
                float* orow = out + (size_t)gr * VV;
#pragma unroll
                for (int nf = 0; nf < 4; nf++) {
                    int gc = col0 + wn + nf * 8 + en;
                    if (gc + 1 < VV) {
                        float2 v = { acc[mf][nf][half * 2]     + __ldg(b_t2 + gc),
                                     acc[mf][nf][half * 2 + 1] + __ldg(b_t2 + gc + 1) };
                        *(float2*)(orow + gc) = v;
                    } else if (gc < VV) {
                        orow[gc] = acc[mf][nf][half * 2] + __ldg(b_t2 + gc);
                    }
                }
            }
        }
    }
}

// ---------------------------------------------------------------------------
// prep 1: fp32 -> bf16 hi/lo splits of ht, hc + counter reset
// ---------------------------------------------------------------------------
__global__ void split_both_k(
    const float* __restrict__ in1, __nv_bfloat16* __restrict__ hi1, __nv_bfloat16* __restrict__ lo1, long n1,
    const float* __restrict__ in2, __nv_bfloat16* __restrict__ hi2, __nv_bfloat16* __restrict__ lo2, long n2)
{
    if (blockIdx.x == 0 && threadIdx.x == 0) { g_ctr[0] = 0; g_ctr[1] = 0; }
    long i = (long)blockIdx.x * blockDim.x + threadIdx.x;
    const float* in; __nv_bfloat16 *hi, *lo;
    if (i < n1) { in = in1; hi = hi1; lo = lo1; }
    else if (i < n1 + n2) { i -= n1; in = in2; hi = hi2; lo = lo2; }
    else return;
    float x = in[i];
    __nv_bfloat16 h = __float2bfloat16(x);
    hi[i] = h;
    lo[i] = __float2bfloat16(x - __bfloat162float(h));
}

// ---------------------------------------------------------------------------
// prep 2: transpose + split (bf16 hi/lo): z=0 -> w_t1, z=1..3 -> w_i1 chunks
// ---------------------------------------------------------------------------
__global__ void tsplit_w_k(const float* __restrict__ w1,
                           const float* __restrict__ wi1,
                           __nv_bfloat16* __restrict__ hi1, __nv_bfloat16* __restrict__ lo1,
                           __nv_bfloat16* __restrict__ hi2, __nv_bfloat16* __restrict__ lo2)
{
    const float* in; __nv_bfloat16 *hi, *lo;
    int z = blockIdx.z;
    if (z == 0) { in = w1; hi = hi1; lo = lo1; }
    else {
        in = wi1 + (long)(z - 1) * DD * HH;
        hi = hi2 + (long)(z - 1) * HH * DD;
        lo = lo2 + (long)(z - 1) * HH * DD;
    }
    __shared__ float t[32][33];
    int n0 = blockIdx.x * 32, k0 = blockIdx.y * 32;
    int n = n0 + threadIdx.x, k = k0 + threadIdx.y;
    t[threadIdx.y][threadIdx.x] = in[(long)k * HH + n];
    __syncthreads();
    int orow = n0 + threadIdx.y, ocol = k0 + threadIdx.x;
    float x = t[threadIdx.x][threadIdx.y];
    __nv_bfloat16 h = __float2bfloat16(x);
    hi[(long)orow * DD + ocol] = h;
    lo[(long)orow * DD + ocol] = __float2bfloat16(x - __bfloat162float(h));
}

// ---------------------------------------------------------------------------
// prep 3: transpose w_t2, fp32 -> fp16  (high occupancy, 1024-thr blocks)
// ---------------------------------------------------------------------------
__global__ void tsplit_h(const float* __restrict__ in, __half* __restrict__ hi,
                         int K, int N)
{
    __shared__ float t[32][33];
    int n0 = blockIdx.x * 32, k0 = blockIdx.y * 32;
    int n = n0 + threadIdx.x, k = k0 + threadIdx.y;
    t[threadIdx.y][threadIdx.x] = (n < N) ? in[(long)k * N + n] : 0.f;
    __syncthreads();
    int orow = n0 + threadIdx.y, ocol = k0 + threadIdx.x;
    hi[(long)orow * K + ocol] = __float2half_rn(t[threadIdx.x][threadIdx.y]);
}

// ---------------------------------------------------------------------------
// IoU combine + mask (high occupancy, 192-thr blocks)
// ---------------------------------------------------------------------------
__global__ __launch_bounds__(192) void iou_mask_k(
    const float* __restrict__ P, const float* __restrict__ w2,
    const float* __restrict__ b2, float* __restrict__ out)
{
    const int idx = blockIdx.x;
    const int e = idx % 33;
    const int s = (idx / 33) % 32;
    const int b = idx / (33 * 32);
    const int c = (s + e) >> 1;
    const int t = threadIdx.x;

    if (t == 100 && idx < 32 * 33) {
        int i = idx / 33, j = idx % 33;
        float v = 0.f;
        int hi = (i + 17 < 33) ? (i + 17) : 33;
        if (j >= i + 1 && j < hi) v = 1.f;
        if (i < 16 && (i & 1) == 0 && j >= 18 + i && ((j - 18 - i) & 1) == 0) v = 1.f;
        out[OUT_MASK_BASE + idx] = v;
    }

    const long CS = (long)MPROJP * HH;
    const float4* ps = (const float4*)(P + (long)(b * 33 + s) * HH);
    const float4* pc = (const float4*)(P + CS + (long)(b * 33 + c) * HH);
    const float4* pe = (const float4*)(P + 2 * CS + (long)(b * 33 + e) * HH);
    const float4* wv = (const float4*)(w2) + t * 3;

    float4 a = ps[t], bb = pc[t], cc = pe[t];
    float v0 = fmaxf(a.x + bb.x + cc.x, 0.f);
    float v1 = fmaxf(a.y + bb.y + cc.y, 0.f);
    float v2 = fmaxf(a.z + bb.z + cc.z, 0.f);
    float v3 = fmaxf(a.w + bb.w + cc.w, 0.f);
    float4 w0 = wv[0], w1 = wv[1], w2v = wv[2];
    float k0 = v0 * w0.x + v1 * w0.w + v2 * w1.z + v3 * w2v.y;
    float k1 = v0 * w0.y + v1 * w1.x + v2 * w1.w + v3 * w2v.z;
    float k2 = v0 * w0.z + v1 * w1.y + v2 * w2v.x + v3 * w2v.w;

#pragma unroll
    for (int off = 16; off; off >>= 1) {
        k0 += __shfl_xor_sync(0xFFFFFFFFu, k0, off);
        k1 += __shfl_xor_sync(0xFFFFFFFFu, k1, off);
        k2 += __shfl_xor_sync(0xFFFFFFFFu, k2, off);
    }
    __shared__ float red[3][6];
    const int lane = t & 31, w = t >> 5;
    if (lane == 0) { red[0][w] = k0; red[1][w] = k1; red[2][w] = k2; }
    __syncthreads();
    if (t == 0) {
        float r0 = __ldg(b2 + 0), r1 = __ldg(b2 + 1), r2 = __ldg(b2 + 2);
#pragma unroll
        for (int i = 0; i < 6; i++) { r0 += red[0][i]; r1 += red[1][i]; r2 += red[2][i]; }
        long base = OUT_IOU_BASE + ((long)b * 3) * (32 * 33) + (long)s * 33 + e;
        out[base + 0 * 32 * 33] = r0;
        out[base + 1 * 32 * 33] = r1;
        out[base + 2 * 32 * 33] = r2;
    }
}

// ---------------------------------------------------------------------------
extern "C" void kernel_launch(void* const* d_in, const int* in_sizes, int n_in,
                              void* d_out, int out_size)
{
    const float* ht   = (const float*)d_in[0];
    const float* hc   = (const float*)d_in[1];
    const float* w_t1 = (const float*)d_in[2];
    const float* b_t1 = (const float*)d_in[3];
    const float* w_t2 = (const float*)d_in[4];
    const float* b_t2 = (const float*)d_in[5];
    const float* w_i1 = (const float*)d_in[6];
    const float* b_i1 = (const float*)d_in[7];
    const float* w_i2 = (const float*)d_in[8];
    const float* b_i2 = (const float*)d_in[9];
    float* out = (float*)d_out;

    float* proj; cudaGetSymbolAddress((void**)&proj, g_proj);
    __nv_bfloat16 *Athi, *Atlo, *Achi, *Aclo;
    __nv_bfloat16 *Bw1hi, *Bw1lo, *Bi1hi, *Bi1lo;
    __half *H1hi, *Bw2hi;
    cudaGetSymbolAddress((void**)&Athi, g_Athi);
    cudaGetSymbolAddress((void**)&Atlo, g_Atlo);
    cudaGetSymbolAddress((void**)&Achi, g_Achi);
    cudaGetSymbolAddress((void**)&Aclo, g_Aclo);
    cudaGetSymbolAddress((void**)&H1hi, g_H1hi);
    cudaGetSymbolAddress((void**)&Bw1hi, g_Bw1hi);
    cudaGetSymbolAddress((void**)&Bw1lo, g_Bw1lo);
    cudaGetSymbolAddress((void**)&Bi1hi, g_Bi1hi);
    cudaGetSymbolAddress((void**)&Bi1lo, g_Bi1lo);
    cudaGetSymbolAddress((void**)&Bw2hi, g_Bw2hi);

    cudaFuncSetAttribute(mega_gemm, cudaFuncAttributeMaxDynamicSharedMemorySize, 98304);

    // prep 1: splits of ht and hc (+ counter reset)
    {
        long n1 = (long)MTXT * DD, n2 = (long)MPROJ * DD;
        split_both_k<<<(int)((n1 + n2 + 255) / 256), 256>>>(
            ht, Athi, Atlo, n1, hc, Achi, Aclo, n2);
    }
    // prep 2: transpose+split w_t1 and w_i1
    tsplit_w_k<<<dim3(24, 24, 4), dim3(32, 32)>>>(w_t1, w_i1, Bw1hi, Bw1lo, Bi1hi, Bi1lo);
    // prep 3: transpose w_t2 (fp16), high occupancy
    tsplit_h<<<dim3(NPAD / 32, 24), dim3(32, 32)>>>(w_t2, Bw2hi, DD, VV);
    // mega GEMM: gemm1 + projections + vocab (1-term fp16)
    mega_gemm<<<G1GRID + PRGRID + VOGRID, 256, 98304>>>(
        Athi, Atlo, Bw1hi, Bw1lo, b_t1, H1hi,
        Achi, Aclo, Bi1hi, Bi1lo, b_i1, proj,
        Bw2hi, b_t2, out);
    // IoU combine + mask, high occupancy
    iou_mask_k<<<BB * TT * (TT + 1), 192>>>(proj, w_i2, b_i2, out);
}

// round 10
// speedup vs baseline: 1.5382x; 1.0580x over previous
#include <cuda_runtime.h>
#include <cuda_bf16.h>
#include <cuda_fp16.h>
#include <cstdint>

// Problem shapes
#define BB 32
#define LL 48
#define DD 768
#define TT 32
#define VV 30522
#define HH 768
#define NPAD 30720   // 120 * 256
#define MPROJ 1056   // 32*33
#define MPROJP 1152
#define MTXT 1536

#define OUT_TEXT_ELEMS ((long)BB * LL * VV)
#define OUT_IOU_ELEMS  ((long)BB * 3 * TT * (TT+1))
#define OUT_IOU_BASE   (OUT_TEXT_ELEMS)
#define OUT_MASK_BASE  (OUT_TEXT_ELEMS + OUT_IOU_ELEMS)

// mega-kernel block ranges
#define G1GRID 72    // gemm1 tiles (12 x 6)
#define PRGRID 162   // projection tiles (9 x 6 x 3)
#define VOGRID 1440  // vocab tiles (12 x 120), 128x256 each

// prep-kernel block ranges
#define SPGRID 7776   // elementwise splits of ht+hc
#define TW1GRID 2304  // w_t1 + w_i1 transpose (24*24*4)
#define TW2GRID 23040 // w_t2 transpose (960 * 24)

// Scratch (device globals; no allocations allowed)
__device__ int   g_ctr[2];
__device__ float g_proj[3L * MPROJP * HH];
__device__ __nv_bfloat16 g_Athi[(long)MTXT * DD],  g_Atlo[(long)MTXT * DD];
__device__ __nv_bfloat16 g_Achi[(long)MPROJ * DD], g_Aclo[(long)MPROJ * DD];
__device__ __half        g_H1hi[(long)MTXT * HH];
__device__ __nv_bfloat16 g_Bw1hi[(long)HH * DD],   g_Bw1lo[(long)HH * DD];
__device__ __nv_bfloat16 g_Bi1hi[3L * HH * DD],    g_Bi1lo[3L * HH * DD];
__device__ __half        g_Bw2hi[(long)NPAD * DD];

// ---------------------------------------------------------------------------
// helpers
// ---------------------------------------------------------------------------
__device__ __forceinline__ uint32_t smem_u32(const void* p) {
    uint32_t a;
    asm("{ .reg .u64 t; cvta.to.shared.u64 t, %1; cvt.u32.u64 %0, t; }" : "=r"(a) : "l"(p));
    return a;
}
__device__ __forceinline__ void cp_async16(uint32_t saddr, const void* gptr) {
    asm volatile("cp.async.cg.shared.global [%0], [%1], 16;" :: "r"(saddr), "l"(gptr));
}
__device__ __forceinline__ void cp_async16z(uint32_t saddr, const void* gptr, bool pred) {
    int sz = pred ? 16 : 0;
    asm volatile("cp.async.cg.shared.global [%0], [%1], 16, %2;"
                 :: "r"(saddr), "l"(gptr), "r"(sz));
}
#define CP_COMMIT()  asm volatile("cp.async.commit_group;" ::: "memory")
#define CP_WAIT2()   asm volatile("cp.async.wait_group 2;" ::: "memory")
#define CP_WAIT1()   asm volatile("cp.async.wait_group 1;" ::: "memory")
#define CP_WAIT0()   asm volatile("cp.async.wait_group 0;" ::: "memory")

#define SWZ(o) ((o) ^ (((o) >> 3) & 0x70))

__device__ __forceinline__ void ldsm_x4(uint32_t addr, uint32_t& r0, uint32_t& r1,
                                        uint32_t& r2, uint32_t& r3) {
    asm volatile("ldmatrix.sync.aligned.m8n8.x4.shared.b16 {%0,%1,%2,%3}, [%4];"
                 : "=r"(r0), "=r"(r1), "=r"(r2), "=r"(r3) : "r"(addr));
}
__device__ __forceinline__ void mma_bf16(float* d, const uint32_t* a, const uint32_t* b) {
    asm volatile(
        "mma.sync.aligned.m16n8k16.row.col.f32.bf16.bf16.f32 "
        "{%0,%1,%2,%3}, {%4,%5,%6,%7}, {%8,%9}, {%0,%1,%2,%3};"
        : "+f"(d[0]), "+f"(d[1]), "+f"(d[2]), "+f"(d[3])
        : "r"(a[0]), "r"(a[1]), "r"(a[2]), "r"(a[3]), "r"(b[0]), "r"(b[1]));
}
__device__ __forceinline__ void mma_f16(float* d, const uint32_t* a, const uint32_t* b) {
    asm volatile(
        "mma.sync.aligned.m16n8k16.row.col.f32.f16.f16.f32 "
        "{%0,%1,%2,%3}, {%4,%5,%6,%7}, {%8,%9}, {%0,%1,%2,%3};"
        : "+f"(d[0]), "+f"(d[1]), "+f"(d[2]), "+f"(d[3])
        : "r"(a[0]), "r"(a[1]), "r"(a[2]), "r"(a[3]), "r"(b[0]), "r"(b[1]));
}

// producer/consumer sync
__device__ __forceinline__ void signal_ctr(int* c) {
    __syncthreads();
    if (threadIdx.x == 0) { __threadfence(); atomicAdd(c, 1); }
}
__device__ __forceinline__ void wait_ctr(int* c, int target) {
    if (threadIdx.x == 0) {
        volatile int* vc = c;
        while (*vc < target) __nanosleep(64);
    }
    __syncthreads();
    __threadfence();
}

// ---------------------------------------------------------------------------
// bf16 3-pass mainloop (tile 128x128, K=768, 3-stage cp.async @32KB)
// ---------------------------------------------------------------------------
#define NCHUNK 36

__device__ __forceinline__ void mainloop_bf16(
    uint32_t sbase, int tid, int wid, int lane, int row0, int col0, int Mclip,
    const __nv_bfloat16* __restrict__ Ahi, const __nv_bfloat16* __restrict__ Alo,
    const __nv_bfloat16* __restrict__ Bhi, const __nv_bfloat16* __restrict__ Blo,
    float acc[4][4][4])
{
    const int wm = (wid & 1) * 64;
    const int wn = (wid >> 1) * 32;
    const int a_m  = lane & 15;
    const int a_kb = (lane >> 4) << 4;
    const int b_n  = (lane & 7) + ((lane >> 4) << 3);
    const int b_kb = ((lane >> 3) & 1) << 4;

#define LOAD_CHUNKB(KC)                                                         \
    {                                                                           \
        int pass = (KC) / 12;                                                   \
        int kk = ((KC) - pass * 12) * 64;                                       \
        const __nv_bfloat16* Ap = (pass == 1) ? Alo : Ahi;                      \
        const __nv_bfloat16* Bp = (pass == 2) ? Blo : Bhi;                      \
        uint32_t sA = sbase + ((KC) % 3) * 32768;                               \
        uint32_t sB = sA + 16384;                                               \
        _Pragma("unroll")                                                       \
        for (int i = 0; i < 4; i++) {                                           \
            int idx = tid + (i << 8);                                           \
            int m = idx >> 3, j = idx & 7;                                      \
            int grow = row0 + m;                                                \
            bool pa = grow < Mclip;                                             \
            cp_async16z(sA + SWZ(m * 128 + j * 16),                             \
                        Ap + (size_t)(pa ? grow : 0) * DD + kk + j * 8, pa);    \
            cp_async16(sB + SWZ(m * 128 + j * 16),                              \
                       Bp + (size_t)(col0 + m) * DD + kk + j * 8);              \
        }                                                                       \
        CP_COMMIT();                                                            \
    }

    LOAD_CHUNKB(0);
    LOAD_CHUNKB(1);
    LOAD_CHUNKB(2);

    for (int kc = 0; kc < NCHUNK; kc++) {
        if (kc < NCHUNK - 2)       { CP_WAIT2(); }
        else if (kc == NCHUNK - 2) { CP_WAIT1(); }
        else                       { CP_WAIT0(); }
        __syncthreads();
        const uint32_t sA = sbase + (kc % 3) * 32768;
        const uint32_t sB = sA + 16384;

#pragma unroll
        for (int k16 = 0; k16 < 4; k16++) {
            const int kb = k16 * 32;
            uint32_t a[4][4], b[2][4];
#pragma unroll
            for (int mf = 0; mf < 4; mf++)
                ldsm_x4(sA + SWZ((wm + mf * 16 + a_m) * 128 + kb + a_kb),
                        a[mf][0], a[mf][1], a[mf][2], a[mf][3]);
#pragma unroll
            for (int np = 0; np < 2; np++)
                ldsm_x4(sB + SWZ((wn + np * 16 + b_n) * 128 + kb + b_kb),
                        b[np][0], b[np][1], b[np][2], b[np][3]);
#pragma unroll
            for (int mf = 0; mf < 4; mf++) {
#pragma unroll
                for (int nf = 0; nf < 4; nf++) {
                    uint32_t bb[2] = { b[nf >> 1][(nf & 1) * 2],
                                       b[nf >> 1][(nf & 1) * 2 + 1] };
                    mma_bf16(acc[mf][nf], a[mf], bb);
                }
            }
        }
        __syncthreads();
        if (kc + 3 < NCHUNK) LOAD_CHUNKB(kc + 3);
    }
#undef LOAD_CHUNKB
}

// ---------------------------------------------------------------------------
// GEMM mega kernel: gemm1 (72) -> proj (162) -> vocab (1440, waits on gemm1)
// vocab: tile 128x256, warp tile 64x64, 3-stage 48KB/stage, 1 CTA/SM.
// ---------------------------------------------------------------------------
__global__ __launch_bounds__(256) void mega_gemm(
    const __nv_bfloat16* __restrict__ Athi, const __nv_bfloat16* __restrict__ Atlo,
    const __nv_bfloat16* __restrict__ Bw1hi, const __nv_bfloat16* __restrict__ Bw1lo,
    const float* __restrict__ b_t1, __half* __restrict__ H1hi,
    const __nv_bfloat16* __restrict__ Achi, const __nv_bfloat16* __restrict__ Aclo,
    const __nv_bfloat16* __restrict__ Bi1hi, const __nv_bfloat16* __restrict__ Bi1lo,
    const float* __restrict__ b_i1, float* __restrict__ proj,
    const __half* __restrict__ Bw2,
    const float* __restrict__ b_t2, float* __restrict__ out)
{
    extern __shared__ char smem[];
    const uint32_t sbase = smem_u32(smem);
    const int tid  = threadIdx.x;
    const int wid  = tid >> 5;
    const int lane = tid & 31;
    const int em = lane >> 2;
    const int en = (lane & 3) * 2;
    const int bid = blockIdx.x;

    if (bid < G1GRID) {
        // ===================== GEMM1: h1 -> fp16 hi =====================
        const int row0 = (bid / 6) * 128;
        const int col0 = (bid % 6) * 128;
        float acc[4][4][4];
#pragma unroll
        for (int i = 0; i < 4; i++)
#pragma unroll
            for (int j = 0; j < 4; j++)
#pragma unroll
                for (int r = 0; r < 4; r++) acc[i][j][r] = 0.f;
        mainloop_bf16(sbase, tid, wid, lane, row0, col0, MTXT,
                      Athi, Atlo, Bw1hi, Bw1lo, acc);
        const int wm = (wid & 1) * 64;
        const int wn = (wid >> 1) * 32;
#pragma unroll
        for (int mf = 0; mf < 4; mf++) {
#pragma unroll
            for (int half = 0; half < 2; half++) {
                int gr = row0 + wm + mf * 16 + em + half * 8;
#pragma unroll
                for (int nf = 0; nf < 4; nf++) {
                    int gc = col0 + wn + nf * 8 + en;
                    float vx = fmaxf(acc[mf][nf][half * 2]     + __ldg(b_t1 + gc), 0.f);
                    float vy = fmaxf(acc[mf][nf][half * 2 + 1] + __ldg(b_t1 + gc + 1), 0.f);
                    __half2 h;
                    h.x = __float2half_rn(vx);
                    h.y = __float2half_rn(vy);
                    *(__half2*)(H1hi + (size_t)gr * HH + gc) = h;
                }
            }
        }
        signal_ctr(&g_ctr[0]);

    } else if (bid < G1GRID + PRGRID) {
        // ===================== projections =====================
        const int p = bid - G1GRID;
        const int col0 = (p % 6) * 128;
        const int row0 = ((p / 6) % 9) * 128;
        const int pz = p / 54;
        float acc[4][4][4];
#pragma unroll
        for (int i = 0; i < 4; i++)
#pragma unroll
            for (int j = 0; j < 4; j++)
#pragma unroll
                for (int r = 0; r < 4; r++) acc[i][j][r] = 0.f;
        mainloop_bf16(sbase, tid, wid, lane, row0, col0, MPROJ,
                      Achi, Aclo, Bi1hi + (long)pz * HH * DD,
                      Bi1lo + (long)pz * HH * DD, acc);
        float* Cf = proj + (long)pz * MPROJP * HH;
        const int wm = (wid & 1) * 64;
        const int wn = (wid >> 1) * 32;
        const bool bias_on = (pz == 0);
#pragma unroll
        for (int mf = 0; mf < 4; mf++) {
#pragma unroll
            for (int half = 0; half < 2; half++) {
                int gr = row0 + wm + mf * 16 + em + half * 8;
#pragma unroll
                for (int nf = 0; nf < 4; nf++) {
                    int gc = col0 + wn + nf * 8 + en;
                    float vx = acc[mf][nf][half * 2];
                    float vy = acc[mf][nf][half * 2 + 1];
                    if (bias_on) { vx += __ldg(b_i1 + gc); vy += __ldg(b_i1 + gc + 1); }
                    float2 v = { vx, vy };
                    *(float2*)(Cf + (size_t)gr * HH + gc) = v;
                }
            }
        }

    } else {
        // ============ vocab GEMM (fp16 1-term, 128x256 tile, 64x64 warps) ============
        wait_ctr(&g_ctr[0], G1GRID);
        const int v = bid - (G1GRID + PRGRID);
        const int col0 = (v % 120) * 256;
        const int row0 = (v / 120) * 128;
        const int wm = (wid & 1) * 64;
        const int wn = (wid >> 1) * 64;
        const int a_m  = lane & 15;
        const int a_kb = (lane >> 4) << 4;
        const int b_n  = (lane & 7) + ((lane >> 4) << 3);
        const int b_kb = ((lane >> 3) & 1) << 4;

        float acc[4][8][4];
#pragma unroll
        for (int i = 0; i < 4; i++)
#pragma unroll
            for (int j = 0; j < 8; j++)
#pragma unroll
                for (int r = 0; r < 4; r++) acc[i][j][r] = 0.f;

#define VCHUNK 12
#define LOAD_CHUNKV(KC)                                                         \
    {                                                                           \
        int kk = (KC) * 64;                                                     \
        uint32_t st = sbase + ((KC) % 3) * 49152;                               \
        _Pragma("unroll")                                                       \
        for (int i = 0; i < 4; i++) {                                           \
            int idx = tid + (i << 8);                                           \
            int m = idx >> 3, j = idx & 7;                                      \
            cp_async16(st + SWZ(m * 128 + j * 16),                              \
                       H1hi + (size_t)(row0 + m) * DD + kk + j * 8);            \
        }                                                                       \
        _Pragma("unroll")                                                       \
        for (int i = 0; i < 8; i++) {                                           \
            int idx = tid + (i << 8);                                           \
            int m = idx >> 3, j = idx & 7;                                      \
            cp_async16(st + 16384 + SWZ(m * 128 + j * 16),                      \
                       Bw2 + (size_t)(col0 + m) * DD + kk + j * 8);             \
        }                                                                       \
        CP_COMMIT();                                                            \
    }

        LOAD_CHUNKV(0);
        LOAD_CHUNKV(1);
        LOAD_CHUNKV(2);

        for (int kc = 0; kc < VCHUNK; kc++) {
            if (kc < VCHUNK - 2)       { CP_WAIT2(); }
            else if (kc == VCHUNK - 2) { CP_WAIT1(); }
            else                       { CP_WAIT0(); }
            __syncthreads();
            const uint32_t sA = sbase + (kc % 3) * 49152;
            const uint32_t sB = sA + 16384;

#pragma unroll
            for (int k16 = 0; k16 < 4; k16++) {
                const int kb = k16 * 32;
                uint32_t a[4][4], b[4][4];
#pragma unroll
                for (int mf = 0; mf < 4; mf++)
                    ldsm_x4(sA + SWZ((wm + mf * 16 + a_m) * 128 + kb + a_kb),
                            a[mf][0], a[mf][1], a[mf][2], a[mf][3]);
#pragma unroll
                for (int np = 0; np < 4; np++)
                    ldsm_x4(sB + SWZ((wn + np * 16 + b_n) * 128 + kb + b_kb),
                            b[np][0], b[np][1], b[np][2], b[np][3]);
#pragma unroll
                for (int mf = 0; mf < 4; mf++) {
#pragma unroll
                    for (int nf = 0; nf < 8; nf++) {
                        uint32_t bb[2] = { b[nf >> 1][(nf & 1) * 2],
                                           b[nf >> 1][(nf & 1) * 2 + 1] };
                        mma_f16(acc[mf][nf], a[mf], bb);
                    }
                }
            }
            __syncthreads();
            if (kc + 3 < VCHUNK) LOAD_CHUNKV(kc + 3);
        }
#undef LOAD_CHUNKV

#pragma unroll
        for (int mf = 0; mf < 4; mf++) {
#pragma unroll
            for (int half = 0; half < 2; half++) {
                int gr = row0 + wm + mf * 16 + em + half * 8;
                float* orow = out + (size_t)gr * VV;
#pragma unroll
                for (int nf = 0; nf < 8; nf++) {
                    int gc = col0 + wn + nf * 8 + en;
                    if (gc + 1 < VV) {
                        float2 vv = { acc[mf][nf][half * 2]     + __ldg(b_t2 + gc),
                                      acc[mf][nf][half * 2 + 1] + __ldg(b_t2 + gc + 1) };
                        *(float2*)(orow + gc) = vv;
                    } else if (gc < VV) {
                        orow[gc] = acc[mf][nf][half * 2] + __ldg(b_t2 + gc);
                    }
                }
            }
        }
    }
}

// ---------------------------------------------------------------------------
// Unified prep kernel (256 threads):
//   [0, SPGRID)                : fp32->bf16 hi/lo splits of ht, hc (+ctr reset)
//   [SPGRID, +TW1GRID)         : transpose+split w_t1 (z=0), w_i1 chunks (z=1..3)
//   [SPGRID+TW1GRID, +TW2GRID) : transpose w_t2 fp32 -> fp16 (NPAD x 768)
// ---------------------------------------------------------------------------
__global__ __launch_bounds__(256) void prep_k(
    const float* __restrict__ ht, const float* __restrict__ hc,
    __nv_bfloat16* __restrict__ Athi, __nv_bfloat16* __restrict__ Atlo,
    __nv_bfloat16* __restrict__ Achi, __nv_bfloat16* __restrict__ Aclo,
    const float* __restrict__ w_t1, const float* __restrict__ w_i1,
    __nv_bfloat16* __restrict__ Bw1hi, __nv_bfloat16* __restrict__ Bw1lo,
    __nv_bfloat16* __restrict__ Bi1hi, __nv_bfloat16* __restrict__ Bi1lo,
    const float* __restrict__ w_t2, __half* __restrict__ Bw2)
{
    const int bid = blockIdx.x;
    const int tid = threadIdx.x;

    if (bid < SPGRID) {
        if (bid == 0 && tid == 0) { g_ctr[0] = 0; g_ctr[1] = 0; }
        long n1 = (long)MTXT * DD, n2 = (long)MPROJ * DD;
        long i = (long)bid * 256 + tid;
        const float* in; __nv_bfloat16 *hi, *lo;
        if (i < n1) { in = ht; hi = Athi; lo = Atlo; }
        else if (i < n1 + n2) { i -= n1; in = hc; hi = Achi; lo = Aclo; }
        else return;
        float x = in[i];
        __nv_bfloat16 h = __float2bfloat16(x);
        hi[i] = h;
        lo[i] = __float2bfloat16(x - __bfloat162float(h));

    } else if (bid < SPGRID + TW1GRID) {
        const int bt = bid - SPGRID;
        const int z = bt / 576;
        const int r = bt % 576;
        const int n0 = (r % 24) * 32;
        const int k0 = (r / 24) * 32;
        const float* in; __nv_bfloat16 *hi, *lo;
        if (z == 0) { in = w_t1; hi = Bw1hi; lo = Bw1lo; }
        else {
            in = w_i1 + (long)(z - 1) * DD * HH;
            hi = Bi1hi + (long)(z - 1) * HH * DD;
            lo = Bi1lo + (long)(z - 1) * HH * DD;
        }
        __shared__ float t1[32][33];
        const int x = tid & 31, y0 = (tid >> 5) * 4;
#pragma unroll
        for (int i = 0; i < 4; i++) {
            int y = y0 + i;
            t1[y][x] = in[(long)(k0 + y) * HH + n0 + x];
        }
        __syncthreads();
#pragma unroll
        for (int i = 0; i < 4; i++) {
            int y = y0 + i;
            float v = t1[x][y];
            __nv_bfloat16 h = __float2bfloat16(v);
            hi[(long)(n0 + y) * DD + k0 + x] = h;
            lo[(long)(n0 + y) * DD + k0 + x] = __float2bfloat16(v - __bfloat162float(h));
        }

    } else {
        const int bt = bid - (SPGRID + TW1GRID);
        const int n0 = (bt % 960) * 32;
        const int k0 = (bt / 960) * 32;
        __shared__ float t2[32][33];
        const int x = tid & 31, y0 = (tid >> 5) * 4;
#pragma unroll
        for (int i = 0; i < 4; i++) {
            int y = y0 + i;
            int n = n0 + x;
            t2[y][x] = (n < VV) ? w_t2[(long)(k0 + y) * VV + n] : 0.f;
        }
        __syncthreads();
#pragma unroll
        for (int i = 0; i < 4; i++) {
            int y = y0 + i;
            Bw2[(long)(n0 + y) * DD + k0 + x] = __float2half_rn(t2[x][y]);
        }
    }
}

// ---------------------------------------------------------------------------
// IoU combine + mask (high occupancy, 192-thr blocks)
// ---------------------------------------------------------------------------
__global__ __launch_bounds__(192) void iou_mask_k(
    const float* __restrict__ P, const float* __restrict__ w2,
    const float* __restrict__ b2, float* __restrict__ out)
{
    const int idx = blockIdx.x;
    const int e = idx % 33;
    const int s = (idx / 33) % 32;
    const int b = idx / (33 * 32);
    const int c = (s + e) >> 1;
    const int t = threadIdx.x;

    if (t == 100 && idx < 32 * 33) {
        int i = idx / 33, j = idx % 33;
        float v = 0.f;
        int hi = (i + 17 < 33) ? (i + 17) : 33;
        if (j >= i + 1 && j < hi) v = 1.f;
        if (i < 16 && (i & 1) == 0 && j >= 18 + i && ((j - 18 - i) & 1) == 0) v = 1.f;
        out[OUT_MASK_BASE + idx] = v;
    }

    const long CS = (long)MPROJP * HH;
    const float4* ps = (const float4*)(P + (long)(b * 33 + s) * HH);
    const float4* pc = (const float4*)(P + CS + (long)(b * 33 + c) * HH);
    const float4* pe = (const float4*)(P + 2 * CS + (long)(b * 33 + e) * HH);
    const float4* wv = (const float4*)(w2) + t * 3;

    float4 a = ps[t], bb = pc[t], cc = pe[t];
    float v0 = fmaxf(a.x + bb.x + cc.x, 0.f);
    float v1 = fmaxf(a.y + bb.y + cc.y, 0.f);
    float v2 = fmaxf(a.z + bb.z + cc.z, 0.f);
    float v3 = fmaxf(a.w + bb.w + cc.w, 0.f);
    float4 w0 = wv[0], w1 = wv[1], w2v = wv[2];
    float k0 = v0 * w0.x + v1 * w0.w + v2 * w1.z + v3 * w2v.y;
    float k1 = v0 * w0.y + v1 * w1.x + v2 * w1.w + v3 * w2v.z;
    float k2 = v0 * w0.z + v1 * w1.y + v2 * w2v.x + v3 * w2v.w;

#pragma unroll
    for (int off = 16; off; off >>= 1) {
        k0 += __shfl_xor_sync(0xFFFFFFFFu, k0, off);
        k1 += __shfl_xor_sync(0xFFFFFFFFu, k1, off);
        k2 += __shfl_xor_sync(0xFFFFFFFFu, k2, off);
    }
    __shared__ float red[3][6];
    const int lane = t & 31, w = t >> 5;
    if (lane == 0) { red[0][w] = k0; red[1][w] = k1; red[2][w] = k2; }
    __syncthreads();
    if (t == 0) {
        float r0 = __ldg(b2 + 0), r1 = __ldg(b2 + 1), r2 = __ldg(b2 + 2);
#pragma unroll
        for (int i = 0; i < 6; i++) { r0 += red[0][i]; r1 += red[1][i]; r2 += red[2][i]; }
        long base = OUT_IOU_BASE + ((long)b * 3) * (32 * 33) + (long)s * 33 + e;
        out[base + 0 * 32 * 33] = r0;
        out[base + 1 * 32 * 33] = r1;
        out[base + 2 * 32 * 33] = r2;
    }
}

// ---------------------------------------------------------------------------
extern "C" void kernel_launch(void* const* d_in, const int* in_sizes, int n_in,
                              void* d_out, int out_size)
{
    const float* ht   = (const float*)d_in[0];
    const float* hc   = (const float*)d_in[1];
    const float* w_t1 = (const float*)d_in[2];
    const float* b_t1 = (const float*)d_in[3];
    const float* w_t2 = (const float*)d_in[4];
    const float* b_t2 = (const float*)d_in[5];
    const float* w_i1 = (const float*)d_in[6];
    const float* b_i1 = (const float*)d_in[7];
    const float* w_i2 = (const float*)d_in[8];
    const float* b_i2 = (const float*)d_in[9];
    float* out = (float*)d_out;

    float* proj; cudaGetSymbolAddress((void**)&proj, g_proj);
    __nv_bfloat16 *Athi, *Atlo, *Achi, *Aclo;
    __nv_bfloat16 *Bw1hi, *Bw1lo, *Bi1hi, *Bi1lo;
    __half *H1hi, *Bw2hi;
    cudaGetSymbolAddress((void**)&Athi, g_Athi);
    cudaGetSymbolAddress((void**)&Atlo, g_Atlo);
    cudaGetSymbolAddress((void**)&Achi, g_Achi);
    cudaGetSymbolAddress((void**)&Aclo, g_Aclo);
    cudaGetSymbolAddress((void**)&H1hi, g_H1hi);
    cudaGetSymbolAddress((void**)&Bw1hi, g_Bw1hi);
    cudaGetSymbolAddress((void**)&Bw1lo, g_Bw1lo);
    cudaGetSymbolAddress((void**)&Bi1hi, g_Bi1hi);
    cudaGetSymbolAddress((void**)&Bi1lo, g_Bi1lo);
    cudaGetSymbolAddress((void**)&Bw2hi, g_Bw2hi);

    cudaFuncSetAttribute(mega_gemm, cudaFuncAttributeMaxDynamicSharedMemorySize, 147456);

    // unified prep
    prep_k<<<SPGRID + TW1GRID + TW2GRID, 256>>>(
        ht, hc, Athi, Atlo, Achi, Aclo,
        w_t1, w_i1, Bw1hi, Bw1lo, Bi1hi, Bi1lo,
        w_t2, Bw2hi);
    // mega GEMM: gemm1 + projections + vocab (1-term fp16, 64x64 warp tiles)
    mega_gemm<<<G1GRID + PRGRID + VOGRID, 256, 147456>>>(
        Athi, Atlo, Bw1hi, Bw1lo, b_t1, H1hi,
        Achi, Aclo, Bi1hi, Bi1lo, b_i1, proj,
        Bw2hi, b_t2, out);
    // IoU combine + mask
    iou_mask_k<<<BB * TT * (TT + 1), 192>>>(proj, w_i2, b_i2, out);
}

// round 11
// speedup vs baseline: 1.5890x; 1.0330x over previous
#include <cuda_runtime.h>
#include <cuda_bf16.h>
#include <cuda_fp16.h>
#include <cstdint>

// Problem shapes
#define BB 32
#define LL 48
#define DD 768
#define TT 32
#define VV 30522
#define HH 768
#define NPAD 30720   // 120 * 256
#define MPROJ 1056   // 32*33
#define MPROJP 1152
#define MTXT 1536

#define OUT_TEXT_ELEMS ((long)BB * LL * VV)
#define OUT_IOU_ELEMS  ((long)BB * 3 * TT * (TT+1))
#define OUT_IOU_BASE   (OUT_TEXT_ELEMS)
#define OUT_MASK_BASE  (OUT_TEXT_ELEMS + OUT_IOU_ELEMS)

// mega-kernel block ranges
#define G1GRID 72    // gemm1 tiles (12 x 6)
#define PRGRID 162   // projection tiles (9 x 6 x 3)
#define VOGRID 1440  // vocab tiles (12 x 120), 128x256 each

// prep-kernel block ranges
#define SPGRID 7776    // elementwise splits of ht+hc
#define TW1GRID 1152   // w_t1 + w_i1 transpose: 4 z * (12 ktiles * 24 ntiles)
#define TW2GRID 11520  // w_t2 transpose: 12 ktiles * 960 ntiles

// Scratch (device globals; no allocations allowed)
__device__ int   g_ctr[16];   // [0..11]: per-row-block gemm1 completion
__device__ float g_proj[3L * MPROJP * HH];
__device__ __nv_bfloat16 g_Athi[(long)MTXT * DD],  g_Atlo[(long)MTXT * DD];
__device__ __nv_bfloat16 g_Achi[(long)MPROJ * DD], g_Aclo[(long)MPROJ * DD];
__device__ __half        g_H1hi[(long)MTXT * HH];
__device__ __nv_bfloat16 g_Bw1hi[(long)HH * DD],   g_Bw1lo[(long)HH * DD];
__device__ __nv_bfloat16 g_Bi1hi[3L * HH * DD],    g_Bi1lo[3L * HH * DD];
__device__ __half        g_Bw2hi[(long)NPAD * DD];

// ---------------------------------------------------------------------------
// helpers
// ---------------------------------------------------------------------------
__device__ __forceinline__ uint32_t smem_u32(const void* p) {
    uint32_t a;
    asm("{ .reg .u64 t; cvta.to.shared.u64 t, %1; cvt.u32.u64 %0, t; }" : "=r"(a) : "l"(p));
    return a;
}
__device__ __forceinline__ void cp_async16(uint32_t saddr, const void* gptr) {
    asm volatile("cp.async.cg.shared.global [%0], [%1], 16;" :: "r"(saddr), "l"(gptr));
}
__device__ __forceinline__ void cp_async16z(uint32_t saddr, const void* gptr, bool pred) {
    int sz = pred ? 16 : 0;
    asm volatile("cp.async.cg.shared.global [%0], [%1], 16, %2;"
                 :: "r"(saddr), "l"(gptr), "r"(sz));
}
#define CP_COMMIT()  asm volatile("cp.async.commit_group;" ::: "memory")
#define CP_WAIT2()   asm volatile("cp.async.wait_group 2;" ::: "memory")
#define CP_WAIT1()   asm volatile("cp.async.wait_group 1;" ::: "memory")
#define CP_WAIT0()   asm volatile("cp.async.wait_group 0;" ::: "memory")

#define SWZ(o) ((o) ^ (((o) >> 3) & 0x70))

__device__ __forceinline__ void ldsm_x4(uint32_t addr, uint32_t& r0, uint32_t& r1,
                                        uint32_t& r2, uint32_t& r3) {
    asm volatile("ldmatrix.sync.aligned.m8n8.x4.shared.b16 {%0,%1,%2,%3}, [%4];"
                 : "=r"(r0), "=r"(r1), "=r"(r2), "=r"(r3) : "r"(addr));
}
__device__ __forceinline__ void mma_bf16(float* d, const uint32_t* a, const uint32_t* b) {
    asm volatile(
        "mma.sync.aligned.m16n8k16.row.col.f32.bf16.bf16.f32 "
        "{%0,%1,%2,%3}, {%4,%5,%6,%7}, {%8,%9}, {%0,%1,%2,%3};"
        : "+f"(d[0]), "+f"(d[1]), "+f"(d[2]), "+f"(d[3])
        : "r"(a[0]), "r"(a[1]), "r"(a[2]), "r"(a[3]), "r"(b[0]), "r"(b[1]));
}
__device__ __forceinline__ void mma_f16(float* d, const uint32_t* a, const uint32_t* b) {
    asm volatile(
        "mma.sync.aligned.m16n8k16.row.col.f32.f16.f16.f32 "
        "{%0,%1,%2,%3}, {%4,%5,%6,%7}, {%8,%9}, {%0,%1,%2,%3};"
        : "+f"(d[0]), "+f"(d[1]), "+f"(d[2]), "+f"(d[3])
        : "r"(a[0]), "r"(a[1]), "r"(a[2]), "r"(a[3]), "r"(b[0]), "r"(b[1]));
}

// producer/consumer sync
__device__ __forceinline__ void signal_ctr(int* c) {
    __syncthreads();
    if (threadIdx.x == 0) { __threadfence(); atomicAdd(c, 1); }
}
__device__ __forceinline__ void wait_ctr(int* c, int target) {
    if (threadIdx.x == 0) {
        volatile int* vc = c;
        while (*vc < target) __nanosleep(64);
    }
    __syncthreads();
    __threadfence();
}

// ---------------------------------------------------------------------------
// bf16 3-pass mainloop (tile 128x128, K=768, 3-stage cp.async @32KB)
// ---------------------------------------------------------------------------
#define NCHUNK 36

__device__ __forceinline__ void mainloop_bf16(
    uint32_t sbase, int tid, int wid, int lane, int row0, int col0, int Mclip,
    const __nv_bfloat16* __restrict__ Ahi, const __nv_bfloat16* __restrict__ Alo,
    const __nv_bfloat16* __restrict__ Bhi, const __nv_bfloat16* __restrict__ Blo,
    float acc[4][4][4])
{
    const int wm = (wid & 1) * 64;
    const int wn = (wid >> 1) * 32;
    const int a_m  = lane & 15;
    const int a_kb = (lane >> 4) << 4;
    const int b_n  = (lane & 7) + ((lane >> 4) << 3);
    const int b_kb = ((lane >> 3) & 1) << 4;

#define LOAD_CHUNKB(KC)                                                         \
    {                                                                           \
        int pass = (KC) / 12;                                                   \
        int kk = ((KC) - pass * 12) * 64;                                       \
        const __nv_bfloat16* Ap = (pass == 1) ? Alo : Ahi;                      \
        const __nv_bfloat16* Bp = (pass == 2) ? Blo : Bhi;                      \
        uint32_t sA = sbase + ((KC) % 3) * 32768;                               \
        uint32_t sB = sA + 16384;                                               \
        _Pragma("unroll")                                                       \
        for (int i = 0; i < 4; i++) {                                           \
            int idx = tid + (i << 8);                                           \
            int m = idx >> 3, j = idx & 7;                                      \
            int grow = row0 + m;                                                \
            bool pa = grow < Mclip;                                             \
            cp_async16z(sA + SWZ(m * 128 + j * 16),                             \
                        Ap + (size_t)(pa ? grow : 0) * DD + kk + j * 8, pa);    \
            cp_async16(sB + SWZ(m * 128 + j * 16),                              \
                       Bp + (size_t)(col0 + m) * DD + kk + j * 8);              \
        }                                                                       \
        CP_COMMIT();                                                            \
    }

    LOAD_CHUNKB(0);
    LOAD_CHUNKB(1);
    LOAD_CHUNKB(2);

    for (int kc = 0; kc < NCHUNK; kc++) {
        if (kc < NCHUNK - 2)       { CP_WAIT2(); }
        else if (kc == NCHUNK - 2) { CP_WAIT1(); }
        else                       { CP_WAIT0(); }
        __syncthreads();
        const uint32_t sA = sbase + (kc % 3) * 32768;
        const uint32_t sB = sA + 16384;

#pragma unroll
        for (int k16 = 0; k16 < 4; k16++) {
            const int kb = k16 * 32;
            uint32_t a[4][4], b[2][4];
#pragma unroll
            for (int mf = 0; mf < 4; mf++)
                ldsm_x4(sA + SWZ((wm + mf * 16 + a_m) * 128 + kb + a_kb),
                        a[mf][0], a[mf][1], a[mf][2], a[mf][3]);
#pragma unroll
            for (int np = 0; np < 2; np++)
                ldsm_x4(sB + SWZ((wn + np * 16 + b_n) * 128 + kb + b_kb),
                        b[np][0], b[np][1], b[np][2], b[np][3]);
#pragma unroll
            for (int mf = 0; mf < 4; mf++) {
#pragma unroll
                for (int nf = 0; nf < 4; nf++) {
                    uint32_t bb[2] = { b[nf >> 1][(nf & 1) * 2],
                                       b[nf >> 1][(nf & 1) * 2 + 1] };
                    mma_bf16(acc[mf][nf], a[mf], bb);
                }
            }
        }
        __syncthreads();
        if (kc + 3 < NCHUNK) LOAD_CHUNKB(kc + 3);
    }
#undef LOAD_CHUNKB
}

// ---------------------------------------------------------------------------
// GEMM mega kernel: gemm1 (72) -> proj (162) -> vocab (1440)
// vocab waits per-row-block: g_ctr[row] == 6.
// ---------------------------------------------------------------------------
__global__ __launch_bounds__(256) void mega_gemm(
    const __nv_bfloat16* __restrict__ Athi, const __nv_bfloat16* __restrict__ Atlo,
    const __nv_bfloat16* __restrict__ Bw1hi, const __nv_bfloat16* __restrict__ Bw1lo,
    const float* __restrict__ b_t1, __half* __restrict__ H1hi,
    const __nv_bfloat16* __restrict__ Achi, const __nv_bfloat16* __restrict__ Aclo,
    const __nv_bfloat16* __restrict__ Bi1hi, const __nv_bfloat16* __restrict__ Bi1lo,
    const float* __restrict__ b_i1, float* __restrict__ proj,
    const __half* __restrict__ Bw2,
    const float* __restrict__ b_t2, float* __restrict__ out)
{
    extern __shared__ char smem[];
    const uint32_t sbase = smem_u32(smem);
    const int tid  = threadIdx.x;
    const int wid  = tid >> 5;
    const int lane = tid & 31;
    const int em = lane >> 2;
    const int en = (lane & 3) * 2;
    const int bid = blockIdx.x;

    if (bid < G1GRID) {
        // ===================== GEMM1: h1 -> fp16 hi =====================
        const int rowblk = bid / 6;
        const int row0 = rowblk * 128;
        const int col0 = (bid % 6) * 128;
        float acc[4][4][4];
#pragma unroll
        for (int i = 0; i < 4; i++)
#pragma unroll
            for (int j = 0; j < 4; j++)
#pragma unroll
                for (int r = 0; r < 4; r++) acc[i][j][r] = 0.f;
        mainloop_bf16(sbase, tid, wid, lane, row0, col0, MTXT,
                      Athi, Atlo, Bw1hi, Bw1lo, acc);
        const int wm = (wid & 1) * 64;
        const int wn = (wid >> 1) * 32;
#pragma unroll
        for (int mf = 0; mf < 4; mf++) {
#pragma unroll
            for (int half = 0; half < 2; half++) {
                int gr = row0 + wm + mf * 16 + em + half * 8;
#pragma unroll
                for (int nf = 0; nf < 4; nf++) {
                    int gc = col0 + wn + nf * 8 + en;
                    float vx = fmaxf(acc[mf][nf][half * 2]     + __ldg(b_t1 + gc), 0.f);
                    float vy = fmaxf(acc[mf][nf][half * 2 + 1] + __ldg(b_t1 + gc + 1), 0.f);
                    __half2 h;
                    h.x = __float2half_rn(vx);
                    h.y = __float2half_rn(vy);
                    *(__half2*)(H1hi + (size_t)gr * HH + gc) = h;
                }
            }
        }
        signal_ctr(&g_ctr[rowblk]);

    } else if (bid < G1GRID + PRGRID) {
        // ===================== projections =====================
        const int p = bid - G1GRID;
        const int col0 = (p % 6) * 128;
        const int row0 = ((p / 6) % 9) * 128;
        const int pz = p / 54;
        float acc[4][4][4];
#pragma unroll
        for (int i = 0; i < 4; i++)
#pragma unroll
            for (int j = 0; j < 4; j++)
#pragma unroll
                for (int r = 0; r < 4; r++) acc[i][j][r] = 0.f;
        mainloop_bf16(sbase, tid, wid, lane, row0, col0, MPROJ,
                      Achi, Aclo, Bi1hi + (long)pz * HH * DD,
                      Bi1lo + (long)pz * HH * DD, acc);
        float* Cf = proj + (long)pz * MPROJP * HH;
        const int wm = (wid & 1) * 64;
        const int wn = (wid >> 1) * 32;
        const bool bias_on = (pz == 0);
#pragma unroll
        for (int mf = 0; mf < 4; mf++) {
#pragma unroll
            for (int half = 0; half < 2; half++) {
                int gr = row0 + wm + mf * 16 + em + half * 8;
#pragma unroll
                for (int nf = 0; nf < 4; nf++) {
                    int gc = col0 + wn + nf * 8 + en;
                    float vx = acc[mf][nf][half * 2];
                    float vy = acc[mf][nf][half * 2 + 1];
                    if (bias_on) { vx += __ldg(b_i1 + gc); vy += __ldg(b_i1 + gc + 1); }
                    float2 v = { vx, vy };
                    *(float2*)(Cf + (size_t)gr * HH + gc) = v;
                }
            }
        }

    } else {
        // ============ vocab GEMM (fp16 1-term, 128x256 tile, 64x64 warps) ============
        const int v = bid - (G1GRID + PRGRID);
        const int col0 = (v % 120) * 256;
        const int rowblk = v / 120;
        const int row0 = rowblk * 128;
        wait_ctr(&g_ctr[rowblk], 6);
        const int wm = (wid & 1) * 64;
        const int wn = (wid >> 1) * 64;
        const int a_m  = lane & 15;
        const int a_kb = (lane >> 4) << 4;
        const int b_n  = (lane & 7) + ((lane >> 4) << 3);
        const int b_kb = ((lane >> 3) & 1) << 4;

        float acc[4][8][4];
#pragma unroll
        for (int i = 0; i < 4; i++)
#pragma unroll
            for (int j = 0; j < 8; j++)
#pragma unroll
                for (int r = 0; r < 4; r++) acc[i][j][r] = 0.f;

#define VCHUNK 12
#define LOAD_CHUNKV(KC)                                                         \
    {                                                                           \
        int kk = (KC) * 64;                                                     \
        uint32_t st = sbase + ((KC) % 3) * 49152;                               \
        _Pragma("unroll")                                                       \
        for (int i = 0; i < 4; i++) {                                           \
            int idx = tid + (i << 8);                                           \
            int m = idx >> 3, j = idx & 7;                                      \
            cp_async16(st + SWZ(m * 128 + j * 16),                              \
                       H1hi + (size_t)(row0 + m) * DD + kk + j * 8);            \
        }                                                                       \
        _Pragma("unroll")                                                       \
        for (int i = 0; i < 8; i++) {                                           \
            int idx = tid + (i << 8);                                           \
            int m = idx >> 3, j = idx & 7;                                      \
            cp_async16(st + 16384 + SWZ(m * 128 + j * 16),                      \
                       Bw2 + (size_t)(col0 + m) * DD + kk + j * 8);             \
        }                                                                       \
        CP_COMMIT();                                                            \
    }

        LOAD_CHUNKV(0);
        LOAD_CHUNKV(1);
        LOAD_CHUNKV(2);

        for (int kc = 0; kc < VCHUNK; kc++) {
            if (kc < VCHUNK - 2)       { CP_WAIT2(); }
            else if (kc == VCHUNK - 2) { CP_WAIT1(); }
            else                       { CP_WAIT0(); }
            __syncthreads();
            const uint32_t sA = sbase + (kc % 3) * 49152;
            const uint32_t sB = sA + 16384;

#pragma unroll
            for (int k16 = 0; k16 < 4; k16++) {
                const int kb = k16 * 32;
                uint32_t a[4][4], b[4][4];
#pragma unroll
                for (int mf = 0; mf < 4; mf++)
                    ldsm_x4(sA + SWZ((wm + mf * 16 + a_m) * 128 + kb + a_kb),
                            a[mf][0], a[mf][1], a[mf][2], a[mf][3]);
#pragma unroll
                for (int np = 0; np < 4; np++)
                    ldsm_x4(sB + SWZ((wn + np * 16 + b_n) * 128 + kb + b_kb),
                            b[np][0], b[np][1], b[np][2], b[np][3]);
#pragma unroll
                for (int mf = 0; mf < 4; mf++) {
#pragma unroll
                    for (int nf = 0; nf < 8; nf++) {
                        uint32_t bb[2] = { b[nf >> 1][(nf & 1) * 2],
                                           b[nf >> 1][(nf & 1) * 2 + 1] };
                        mma_f16(acc[mf][nf], a[mf], bb);
                    }
                }
            }
            __syncthreads();
            if (kc + 3 < VCHUNK) LOAD_CHUNKV(kc + 3);
        }
#undef LOAD_CHUNKV

#pragma unroll
        for (int mf = 0; mf < 4; mf++) {
#pragma unroll
            for (int half = 0; half < 2; half++) {
                int gr = row0 + wm + mf * 16 + em + half * 8;
                float* orow = out + (size_t)gr * VV;
#pragma unroll
                for (int nf = 0; nf < 8; nf++) {
                    int gc = col0 + wn + nf * 8 + en;
                    if (gc + 1 < VV) {
                        float2 vv = { acc[mf][nf][half * 2]     + __ldg(b_t2 + gc),
                                      acc[mf][nf][half * 2 + 1] + __ldg(b_t2 + gc + 1) };
                        *(float2*)(orow + gc) = vv;
                    } else if (gc < VV) {
                        orow[gc] = acc[mf][nf][half * 2] + __ldg(b_t2 + gc);
                    }
                }
            }
        }
    }
}

// ---------------------------------------------------------------------------
// Unified prep kernel (256 threads), coalesced transposes:
//   [0, SPGRID)                : fp32->bf16 hi/lo splits of ht, hc (+ctr reset)
//   [SPGRID, +TW1GRID)         : transpose+split w_t1/w_i1, 64k x 32n tiles
//   [SPGRID+TW1GRID, +TW2GRID) : transpose w_t2 -> fp16, 64k x 32n tiles
// ---------------------------------------------------------------------------
__global__ __launch_bounds__(256) void prep_k(
    const float* __restrict__ ht, const float* __restrict__ hc,
    __nv_bfloat16* __restrict__ Athi, __nv_bfloat16* __restrict__ Atlo,
    __nv_bfloat16* __restrict__ Achi, __nv_bfloat16* __restrict__ Aclo,
    const float* __restrict__ w_t1, const float* __restrict__ w_i1,
    __nv_bfloat16* __restrict__ Bw1hi, __nv_bfloat16* __restrict__ Bw1lo,
    __nv_bfloat16* __restrict__ Bi1hi, __nv_bfloat16* __restrict__ Bi1lo,
    const float* __restrict__ w_t2, __half* __restrict__ Bw2)
{
    const int bid = blockIdx.x;
    const int tid = threadIdx.x;

    if (bid < SPGRID) {
        if (bid == 0 && tid < 16) g_ctr[tid] = 0;
        long n1 = (long)MTXT * DD, n2 = (long)MPROJ * DD;
        long i = (long)bid * 256 + tid;
        const float* in; __nv_bfloat16 *hi, *lo;
        if (i < n1) { in = ht; hi = Athi; lo = Atlo; }
        else if (i < n1 + n2) { i -= n1; in = hc; hi = Achi; lo = Aclo; }
        else return;
        float x = in[i];
        __nv_bfloat16 h = __float2bfloat16(x);
        hi[i] = h;
        lo[i] = __float2bfloat16(x - __bfloat162float(h));

    } else if (bid < SPGRID + TW1GRID) {
        // w_t1 / w_i1: 64k x 32n tile; in is (768 x 768) row-major (k-major rows)
        const int bt = bid - SPGRID;
        const int z  = bt / 288;
        const int r  = bt % 288;
        const int k0 = (r / 24) * 64;
        const int n0 = (r % 24) * 32;
        const float* in; __nv_bfloat16 *hi, *lo;
        if (z == 0) { in = w_t1; hi = Bw1hi; lo = Bw1lo; }
        else {
            in = w_i1 + (long)(z - 1) * DD * HH;
            hi = Bi1hi + (long)(z - 1) * HH * DD;
            lo = Bi1lo + (long)(z - 1) * HH * DD;
        }
        __shared__ float t1[64][33];
        const int x = tid & 31, y0 = tid >> 5;
#pragma unroll
        for (int i = 0; i < 8; i++) {
            int y = y0 + i * 8;
            t1[y][x] = in[(long)(k0 + y) * HH + n0 + x];
        }
        __syncthreads();
        // write: warp wr handles rows n = wr + i*8; lane = k-pair
        const int lane = tid & 31, wr = tid >> 5;
#pragma unroll
        for (int i = 0; i < 4; i++) {
            int n = wr + i * 8;
            if (n >= 32) break;
            float v0 = t1[2 * lane][n], v1 = t1[2 * lane + 1][n];
            __nv_bfloat162 h2, l2;
            h2.x = __float2bfloat16(v0);
            h2.y = __float2bfloat16(v1);
            l2.x = __float2bfloat16(v0 - __bfloat162float(h2.x));
            l2.y = __float2bfloat16(v1 - __bfloat162float(h2.y));
            long o = (long)(n0 + n) * DD + k0 + 2 * lane;
            *(__nv_bfloat162*)(hi + o) = h2;
            *(__nv_bfloat162*)(lo + o) = l2;
        }
        // second set of rows (8 warps x 4 iters covers 32 rows exactly)

    } else {
        // w_t2: 64k x 32n tile; in is (768 x 30522) row-major
        const int bt = bid - (SPGRID + TW1GRID);
        const int k0 = (bt / 960) * 64;
        const int n0 = (bt % 960) * 32;
        __shared__ float t2[64][33];
        const int x = tid & 31, y0 = tid >> 5;
#pragma unroll
        for (int i = 0; i < 8; i++) {
            int y = y0 + i * 8;
            int n = n0 + x;
            t2[y][x] = (n < VV) ? w_t2[(long)(k0 + y) * VV + n] : 0.f;
        }
        __syncthreads();
        const int lane = tid & 31, wr = tid >> 5;
#pragma unroll
        for (int i = 0; i < 4; i++) {
            int n = wr + i * 8;
            __half2 h2;
            h2.x = __float2half_rn(t2[2 * lane][n]);
            h2.y = __float2half_rn(t2[2 * lane + 1][n]);
            *(__half2*)(Bw2 + (long)(n0 + n) * DD + k0 + 2 * lane) = h2;
        }
    }
}

// ---------------------------------------------------------------------------
// IoU combine + mask (high occupancy, 192-thr blocks)
// ---------------------------------------------------------------------------
__global__ __launch_bounds__(192) void iou_mask_k(
    const float* __restrict__ P, const float* __restrict__ w2,
    const float* __restrict__ b2, float* __restrict__ out)
{
    const int idx = blockIdx.x;
    const int e = idx % 33;
    const int s = (idx / 33) % 32;
    const int b = idx / (33 * 32);
    const int c = (s + e) >> 1;
    const int t = threadIdx.x;

    if (t == 100 && idx < 32 * 33) {
        int i = idx / 33, j = idx % 33;
        float v = 0.f;
        int hi = (i + 17 < 33) ? (i + 17) : 33;
        if (j >= i + 1 && j < hi) v = 1.f;
        if (i < 16 && (i & 1) == 0 && j >= 18 + i && ((j - 18 - i) & 1) == 0) v = 1.f;
        out[OUT_MASK_BASE + idx] = v;
    }

    const long CS = (long)MPROJP * HH;
    const float4* ps = (const float4*)(P + (long)(b * 33 + s) * HH);
    const float4* pc = (const float4*)(P + CS + (long)(b * 33 + c) * HH);
    const float4* pe = (const float4*)(P + 2 * CS + (long)(b * 33 + e) * HH);
    const float4* wv = (const float4*)(w2) + t * 3;

    float4 a = ps[t], bb = pc[t], cc = pe[t];
    float v0 = fmaxf(a.x + bb.x + cc.x, 0.f);
    float v1 = fmaxf(a.y + bb.y + cc.y, 0.f);
    float v2 = fmaxf(a.z + bb.z + cc.z, 0.f);
    float v3 = fmaxf(a.w + bb.w + cc.w, 0.f);
    float4 w0 = wv[0], w1 = wv[1], w2v = wv[2];
    float k0 = v0 * w0.x + v1 * w0.w + v2 * w1.z + v3 * w2v.y;
    float k1 = v0 * w0.y + v1 * w1.x + v2 * w1.w + v3 * w2v.z;
    float k2 = v0 * w0.z + v1 * w1.y + v2 * w2v.x + v3 * w2v.w;

#pragma unroll
    for (int off = 16; off; off >>= 1) {
        k0 += __shfl_xor_sync(0xFFFFFFFFu, k0, off);
        k1 += __shfl_xor_sync(0xFFFFFFFFu, k1, off);
        k2 += __shfl_xor_sync(0xFFFFFFFFu, k2, off);
    }
    __shared__ float red[3][6];
    const int lane = t & 31, w = t >> 5;
    if (lane == 0) { red[0][w] = k0; red[1][w] = k1; red[2][w] = k2; }
    __syncthreads();
    if (t == 0) {
        float r0 = __ldg(b2 + 0), r1 = __ldg(b2 + 1), r2 = __ldg(b2 + 2);
#pragma unroll
        for (int i = 0; i < 6; i++) { r0 += red[0][i]; r1 += red[1][i]; r2 += red[2][i]; }
        long base = OUT_IOU_BASE + ((long)b * 3) * (32 * 33) + (long)s * 33 + e;
        out[base + 0 * 32 * 33] = r0;
        out[base + 1 * 32 * 33] = r1;
        out[base + 2 * 32 * 33] = r2;
    }
}

// ---------------------------------------------------------------------------
extern "C" void kernel_launch(void* const* d_in, const int* in_sizes, int n_in,
                              void* d_out, int out_size)
{
    const float* ht   = (const float*)d_in[0];
    const float* hc   = (const float*)d_in[1];
    const float* w_t1 = (const float*)d_in[2];
    const float* b_t1 = (const float*)d_in[3];
    const float* w_t2 = (const float*)d_in[4];
    const float* b_t2 = (const float*)d_in[5];
    const float* w_i1 = (const float*)d_in[6];
    const float* b_i1 = (const float*)d_in[7];
    const float* w_i2 = (const float*)d_in[8];
    const float* b_i2 = (const float*)d_in[9];
    float* out = (float*)d_out;

    float* proj; cudaGetSymbolAddress((void**)&proj, g_proj);
    __nv_bfloat16 *Athi, *Atlo, *Achi, *Aclo;
    __nv_bfloat16 *Bw1hi, *Bw1lo, *Bi1hi, *Bi1lo;
    __half *H1hi, *Bw2hi;
    cudaGetSymbolAddress((void**)&Athi, g_Athi);
    cudaGetSymbolAddress((void**)&Atlo, g_Atlo);
    cudaGetSymbolAddress((void**)&Achi, g_Achi);
    cudaGetSymbolAddress((void**)&Aclo, g_Aclo);
    cudaGetSymbolAddress((void**)&H1hi, g_H1hi);
    cudaGetSymbolAddress((void**)&Bw1hi, g_Bw1hi);
    cudaGetSymbolAddress((void**)&Bw1lo, g_Bw1lo);
    cudaGetSymbolAddress((void**)&Bi1hi, g_Bi1hi);
    cudaGetSymbolAddress((void**)&Bi1lo, g_Bi1lo);
    cudaGetSymbolAddress((void**)&Bw2hi, g_Bw2hi);

    cudaFuncSetAttribute(mega_gemm, cudaFuncAttributeMaxDynamicSharedMemorySize, 147456);

    // unified prep (coalesced transposes)
    prep_k<<<SPGRID + TW1GRID + TW2GRID, 256>>>(
        ht, hc, Athi, Atlo, Achi, Aclo,
        w_t1, w_i1, Bw1hi, Bw1lo, Bi1hi, Bi1lo,
        w_t2, Bw2hi);
    // mega GEMM: gemm1 + projections + vocab (per-row-block counters)
    mega_gemm<<<G1GRID + PRGRID + VOGRID, 256, 147456>>>(
        Athi, Atlo, Bw1hi, Bw1lo, b_t1, H1hi,
        Achi, Aclo, Bi1hi, Bi1lo, b_i1, proj,
        Bw2hi, b_t2, out);
    // IoU combine + mask
    iou_mask_k<<<BB * TT * (TT + 1), 192>>>(proj, w_i2, b_i2, out);
}

// round 12
// speedup vs baseline: 1.6037x; 1.0093x over previous
#include <cuda_runtime.h>
#include <cuda_bf16.h>
#include <cuda_fp16.h>
#include <cstdint>

// Problem shapes
#define BB 32
#define LL 48
#define DD 768
#define TT 32
#define VV 30522
#define HH 768
#define NPAD 30720   // 120 * 256
#define MPROJ 1056   // 32*33
#define MPROJP 1152
#define MTXT 1536

#define OUT_TEXT_ELEMS ((long)BB * LL * VV)
#define OUT_IOU_ELEMS  ((long)BB * 3 * TT * (TT+1))
#define OUT_IOU_BASE   (OUT_TEXT_ELEMS)
#define OUT_MASK_BASE  (OUT_TEXT_ELEMS + OUT_IOU_ELEMS)

// mega-kernel block ranges
#define G1GRID 72    // gemm1 tiles (12 x 6)
#define PRGRID 162   // projection tiles (9 x 6 x 3)
#define VOGRID 1440  // vocab tiles (12 x 120), 128x256 each

// prep-kernel block ranges
#define SPGRID 7776    // elementwise splits of ht+hc
#define TW1GRID 1152   // w_t1 + w_i1 transpose: 4 z * (12 ktiles * 24 ntiles)
#define TW2GRID 11520  // w_t2 transpose: 12 ktiles * 960 ntiles

// Scratch (device globals; no allocations allowed)
__device__ int    g_ctr[16];   // [0..11]: per-row-block gemm1 completion
__device__ __half g_proj[3L * MPROJP * HH];   // fp16 projections
__device__ __nv_bfloat16 g_Athi[(long)MTXT * DD],  g_Atlo[(long)MTXT * DD];
__device__ __nv_bfloat16 g_Achi[(long)MPROJ * DD], g_Aclo[(long)MPROJ * DD];
__device__ __half        g_H1hi[(long)MTXT * HH];
__device__ __nv_bfloat16 g_Bw1hi[(long)HH * DD],   g_Bw1lo[(long)HH * DD];
__device__ __nv_bfloat16 g_Bi1hi[3L * HH * DD],    g_Bi1lo[3L * HH * DD];
__device__ __half        g_Bw2hi[(long)NPAD * DD];

// ---------------------------------------------------------------------------
// helpers
// ---------------------------------------------------------------------------
__device__ __forceinline__ uint32_t smem_u32(const void* p) {
    uint32_t a;
    asm("{ .reg .u64 t; cvta.to.shared.u64 t, %1; cvt.u32.u64 %0, t; }" : "=r"(a) : "l"(p));
    return a;
}
__device__ __forceinline__ void cp_async16(uint32_t saddr, const void* gptr) {
    asm volatile("cp.async.cg.shared.global [%0], [%1], 16;" :: "r"(saddr), "l"(gptr));
}
__device__ __forceinline__ void cp_async16z(uint32_t saddr, const void* gptr, bool pred) {
    int sz = pred ? 16 : 0;
    asm volatile("cp.async.cg.shared.global [%0], [%1], 16, %2;"
                 :: "r"(saddr), "l"(gptr), "r"(sz));
}
#define CP_COMMIT()  asm volatile("cp.async.commit_group;" ::: "memory")
#define CP_WAIT2()   asm volatile("cp.async.wait_group 2;" ::: "memory")
#define CP_WAIT1()   asm volatile("cp.async.wait_group 1;" ::: "memory")
#define CP_WAIT0()   asm volatile("cp.async.wait_group 0;" ::: "memory")

#define SWZ(o) ((o) ^ (((o) >> 3) & 0x70))

__device__ __forceinline__ void ldsm_x4(uint32_t addr, uint32_t& r0, uint32_t& r1,
                                        uint32_t& r2, uint32_t& r3) {
    asm volatile("ldmatrix.sync.aligned.m8n8.x4.shared.b16 {%0,%1,%2,%3}, [%4];"
                 : "=r"(r0), "=r"(r1), "=r"(r2), "=r"(r3) : "r"(addr));
}
__device__ __forceinline__ void mma_bf16(float* d, const uint32_t* a, const uint32_t* b) {
    asm volatile(
        "mma.sync.aligned.m16n8k16.row.col.f32.bf16.bf16.f32 "
        "{%0,%1,%2,%3}, {%4,%5,%6,%7}, {%8,%9}, {%0,%1,%2,%3};"
        : "+f"(d[0]), "+f"(d[1]), "+f"(d[2]), "+f"(d[3])
        : "r"(a[0]), "r"(a[1]), "r"(a[2]), "r"(a[3]), "r"(b[0]), "r"(b[1]));
}
__device__ __forceinline__ void mma_f16(float* d, const uint32_t* a, const uint32_t* b) {
    asm volatile(
        "mma.sync.aligned.m16n8k16.row.col.f32.f16.f16.f32 "
        "{%0,%1,%2,%3}, {%4,%5,%6,%7}, {%8,%9}, {%0,%1,%2,%3};"
        : "+f"(d[0]), "+f"(d[1]), "+f"(d[2]), "+f"(d[3])
        : "r"(a[0]), "r"(a[1]), "r"(a[2]), "r"(a[3]), "r"(b[0]), "r"(b[1]));
}

// producer/consumer sync
__device__ __forceinline__ void signal_ctr(int* c) {
    __syncthreads();
    if (threadIdx.x == 0) { __threadfence(); atomicAdd(c, 1); }
}
__device__ __forceinline__ void wait_ctr(int* c, int target) {
    if (threadIdx.x == 0) {
        volatile int* vc = c;
        while (*vc < target) __nanosleep(64);
    }
    __syncthreads();
    __threadfence();
}

// ---------------------------------------------------------------------------
// bf16 3-pass mainloop (tile 128x128, K=768, 3-stage cp.async @32KB)
// ---------------------------------------------------------------------------
#define NCHUNK 36

__device__ __forceinline__ void mainloop_bf16(
    uint32_t sbase, int tid, int wid, int lane, int row0, int col0, int Mclip,
    const __nv_bfloat16* __restrict__ Ahi, const __nv_bfloat16* __restrict__ Alo,
    const __nv_bfloat16* __restrict__ Bhi, const __nv_bfloat16* __restrict__ Blo,
    float acc[4][4][4])
{
    const int wm = (wid & 1) * 64;
    const int wn = (wid >> 1) * 32;
    const int a_m  = lane & 15;
    const int a_kb = (lane >> 4) << 4;
    const int b_n  = (lane & 7) + ((lane >> 4) << 3);
    const int b_kb = ((lane >> 3) & 1) << 4;

#define LOAD_CHUNKB(KC)                                                         \
    {                                                                           \
        int pass = (KC) / 12;                                                   \
        int kk = ((KC) - pass * 12) * 64;                                       \
        const __nv_bfloat16* Ap = (pass == 1) ? Alo : Ahi;                      \
        const __nv_bfloat16* Bp = (pass == 2) ? Blo : Bhi;                      \
        uint32_t sA = sbase + ((KC) % 3) * 32768;                               \
        uint32_t sB = sA + 16384;                                               \
        _Pragma("unroll")                                                       \
        for (int i = 0; i < 4; i++) {                                           \
            int idx = tid + (i << 8);                                           \
            int m = idx >> 3, j = idx & 7;                                      \
            int grow = row0 + m;                                                \
            bool pa = grow < Mclip;                                             \
            cp_async16z(sA + SWZ(m * 128 + j * 16),                             \
                        Ap + (size_t)(pa ? grow : 0) * DD + kk + j * 8, pa);    \
            cp_async16(sB + SWZ(m * 128 + j * 16),                              \
                       Bp + (size_t)(col0 + m) * DD + kk + j * 8);              \
        }                                                                       \
        CP_COMMIT();                                                            \
    }

    LOAD_CHUNKB(0);
    LOAD_CHUNKB(1);
    LOAD_CHUNKB(2);

    for (int kc = 0; kc < NCHUNK; kc++) {
        if (kc < NCHUNK - 2)       { CP_WAIT2(); }
        else if (kc == NCHUNK - 2) { CP_WAIT1(); }
        else                       { CP_WAIT0(); }
        __syncthreads();
        const uint32_t sA = sbase + (kc % 3) * 32768;
        const uint32_t sB = sA + 16384;

#pragma unroll
        for (int k16 = 0; k16 < 4; k16++) {
            const int kb = k16 * 32;
            uint32_t a[4][4], b[2][4];
#pragma unroll
            for (int mf = 0; mf < 4; mf++)
                ldsm_x4(sA + SWZ((wm + mf * 16 + a_m) * 128 + kb + a_kb),
                        a[mf][0], a[mf][1], a[mf][2], a[mf][3]);
#pragma unroll
            for (int np = 0; np < 2; np++)
                ldsm_x4(sB + SWZ((wn + np * 16 + b_n) * 128 + kb + b_kb),
                        b[np][0], b[np][1], b[np][2], b[np][3]);
#pragma unroll
            for (int mf = 0; mf < 4; mf++) {
#pragma unroll
                for (int nf = 0; nf < 4; nf++) {
                    uint32_t bb[2] = { b[nf >> 1][(nf & 1) * 2],
                                       b[nf >> 1][(nf & 1) * 2 + 1] };
                    mma_bf16(acc[mf][nf], a[mf], bb);
                }
            }
        }
        __syncthreads();
        if (kc + 3 < NCHUNK) LOAD_CHUNKB(kc + 3);
    }
#undef LOAD_CHUNKB
}

// ---------------------------------------------------------------------------
// GEMM mega kernel: gemm1 (72) -> proj (162) -> vocab (1440)
// vocab waits per-row-block: g_ctr[row] == 6.
// ---------------------------------------------------------------------------
__global__ __launch_bounds__(256) void mega_gemm(
    const __nv_bfloat16* __restrict__ Athi, const __nv_bfloat16* __restrict__ Atlo,
    const __nv_bfloat16* __restrict__ Bw1hi, const __nv_bfloat16* __restrict__ Bw1lo,
    const float* __restrict__ b_t1, __half* __restrict__ H1hi,
    const __nv_bfloat16* __restrict__ Achi, const __nv_bfloat16* __restrict__ Aclo,
    const __nv_bfloat16* __restrict__ Bi1hi, const __nv_bfloat16* __restrict__ Bi1lo,
    const float* __restrict__ b_i1, __half* __restrict__ proj,
    const __half* __restrict__ Bw2,
    const float* __restrict__ b_t2, float* __restrict__ out)
{
    extern __shared__ char smem[];
    const uint32_t sbase = smem_u32(smem);
    const int tid  = threadIdx.x;
    const int wid  = tid >> 5;
    const int lane = tid & 31;
    const int em = lane >> 2;
    const int en = (lane & 3) * 2;
    const int bid = blockIdx.x;

    if (bid < G1GRID) {
        // ===================== GEMM1: h1 -> fp16 hi =====================
        const int rowblk = bid / 6;
        const int row0 = rowblk * 128;
        const int col0 = (bid % 6) * 128;
        float acc[4][4][4];
#pragma unroll
        for (int i = 0; i < 4; i++)
#pragma unroll
            for (int j = 0; j < 4; j++)
#pragma unroll
                for (int r = 0; r < 4; r++) acc[i][j][r] = 0.f;
        mainloop_bf16(sbase, tid, wid, lane, row0, col0, MTXT,
                      Athi, Atlo, Bw1hi, Bw1lo, acc);
        const int wm = (wid & 1) * 64;
        const int wn = (wid >> 1) * 32;
#pragma unroll
        for (int mf = 0; mf < 4; mf++) {
#pragma unroll
            for (int half = 0; half < 2; half++) {
                int gr = row0 + wm + mf * 16 + em + half * 8;
#pragma unroll
                for (int nf = 0; nf < 4; nf++) {
                    int gc = col0 + wn + nf * 8 + en;
                    float vx = fmaxf(acc[mf][nf][half * 2]     + __ldg(b_t1 + gc), 0.f);
                    float vy = fmaxf(acc[mf][nf][half * 2 + 1] + __ldg(b_t1 + gc + 1), 0.f);
                    __half2 h;
                    h.x = __float2half_rn(vx);
                    h.y = __float2half_rn(vy);
                    *(__half2*)(H1hi + (size_t)gr * HH + gc) = h;
                }
            }
        }
        signal_ctr(&g_ctr[rowblk]);

    } else if (bid < G1GRID + PRGRID) {
        // ===================== projections (fp16 out) =====================
        const int p = bid - G1GRID;
        const int col0 = (p % 6) * 128;
        const int row0 = ((p / 6) % 9) * 128;
        const int pz = p / 54;
        float acc[4][4][4];
#pragma unroll
        for (int i = 0; i < 4; i++)
#pragma unroll
            for (int j = 0; j < 4; j++)
#pragma unroll
                for (int r = 0; r < 4; r++) acc[i][j][r] = 0.f;
        mainloop_bf16(sbase, tid, wid, lane, row0, col0, MPROJ,
                      Achi, Aclo, Bi1hi + (long)pz * HH * DD,
                      Bi1lo + (long)pz * HH * DD, acc);
        __half* Cf = proj + (long)pz * MPROJP * HH;
        const int wm = (wid & 1) * 64;
        const int wn = (wid >> 1) * 32;
        const bool bias_on = (pz == 0);
#pragma unroll
        for (int mf = 0; mf < 4; mf++) {
#pragma unroll
            for (int half = 0; half < 2; half++) {
                int gr = row0 + wm + mf * 16 + em + half * 8;
#pragma unroll
                for (int nf = 0; nf < 4; nf++) {
                    int gc = col0 + wn + nf * 8 + en;
                    float vx = acc[mf][nf][half * 2];
                    float vy = acc[mf][nf][half * 2 + 1];
                    if (bias_on) { vx += __ldg(b_i1 + gc); vy += __ldg(b_i1 + gc + 1); }
                    __half2 h;
                    h.x = __float2half_rn(vx);
                    h.y = __float2half_rn(vy);
                    *(__half2*)(Cf + (size_t)gr * HH + gc) = h;
                }
            }
        }

    } else {
        // ============ vocab GEMM (fp16 1-term, 128x256 tile, 64x64 warps) ============
        const int v = bid - (G1GRID + PRGRID);
        const int col0 = (v % 120) * 256;
        const int rowblk = v / 120;
        const int row0 = rowblk * 128;
        wait_ctr(&g_ctr[rowblk], 6);
        const int wm = (wid & 1) * 64;
        const int wn = (wid >> 1) * 64;
        const int a_m  = lane & 15;
        const int a_kb = (lane >> 4) << 4;
        const int b_n  = (lane & 7) + ((lane >> 4) << 3);
        const int b_kb = ((lane >> 3) & 1) << 4;

        float acc[4][8][4];
#pragma unroll
        for (int i = 0; i < 4; i++)
#pragma unroll
            for (int j = 0; j < 8; j++)
#pragma unroll
                for (int r = 0; r < 4; r++) acc[i][j][r] = 0.f;

#define VCHUNK 12
#define LOAD_CHUNKV(KC)                                                         \
    {                                                                           \
        int kk = (KC) * 64;                                                     \
        uint32_t st = sbase + ((KC) % 3) * 49152;                               \
        _Pragma("unroll")                                                       \
        for (int i = 0; i < 4; i++) {                                           \
            int idx = tid + (i << 8);                                           \
            int m = idx >> 3, j = idx & 7;                                      \
            cp_async16(st + SWZ(m * 128 + j * 16),                              \
                       H1hi + (size_t)(row0 + m) * DD + kk + j * 8);            \
        }                                                                       \
        _Pragma("unroll")                                                       \
        for (int i = 0; i < 8; i++) {                                           \
            int idx = tid + (i << 8);                                           \
            int m = idx >> 3, j = idx & 7;                                      \
            cp_async16(st + 16384 + SWZ(m * 128 + j * 16),                      \
                       Bw2 + (size_t)(col0 + m) * DD + kk + j * 8);             \
        }                                                                       \
        CP_COMMIT();                                                            \
    }

        LOAD_CHUNKV(0);
        LOAD_CHUNKV(1);
        LOAD_CHUNKV(2);

        for (int kc = 0; kc < VCHUNK; kc++) {
            if (kc < VCHUNK - 2)       { CP_WAIT2(); }
            else if (kc == VCHUNK - 2) { CP_WAIT1(); }
            else                       { CP_WAIT0(); }
            __syncthreads();
            const uint32_t sA = sbase + (kc % 3) * 49152;
            const uint32_t sB = sA + 16384;

#pragma unroll
            for (int k16 = 0; k16 < 4; k16++) {
                const int kb = k16 * 32;
                uint32_t a[4][4], b[4][4];
#pragma unroll
                for (int mf = 0; mf < 4; mf++)
                    ldsm_x4(sA + SWZ((wm + mf * 16 + a_m) * 128 + kb + a_kb),
                            a[mf][0], a[mf][1], a[mf][2], a[mf][3]);
#pragma unroll
                for (int np = 0; np < 4; np++)
                    ldsm_x4(sB + SWZ((wn + np * 16 + b_n) * 128 + kb + b_kb),
                            b[np][0], b[np][1], b[np][2], b[np][3]);
#pragma unroll
                for (int mf = 0; mf < 4; mf++) {
#pragma unroll
                    for (int nf = 0; nf < 8; nf++) {
                        uint32_t bb[2] = { b[nf >> 1][(nf & 1) * 2],
                                           b[nf >> 1][(nf & 1) * 2 + 1] };
                        mma_f16(acc[mf][nf], a[mf], bb);
                    }
                }
            }
            __syncthreads();
            if (kc + 3 < VCHUNK) LOAD_CHUNKV(kc + 3);
        }
#undef LOAD_CHUNKV

#pragma unroll
        for (int mf = 0; mf < 4; mf++) {
#pragma unroll
            for (int half = 0; half < 2; half++) {
                int gr = row0 + wm + mf * 16 + em + half * 8;
                float* orow = out + (size_t)gr * VV;
#pragma unroll
                for (int nf = 0; nf < 8; nf++) {
                    int gc = col0 + wn + nf * 8 + en;
                    if (gc + 1 < VV) {
                        float2 vv = { acc[mf][nf][half * 2]     + __ldg(b_t2 + gc),
                                      acc[mf][nf][half * 2 + 1] + __ldg(b_t2 + gc + 1) };
                        *(float2*)(orow + gc) = vv;
                    } else if (gc < VV) {
                        orow[gc] = acc[mf][nf][half * 2] + __ldg(b_t2 + gc);
                    }
                }
            }
        }
    }
}

// ---------------------------------------------------------------------------
// Unified prep kernel (256 threads), coalesced transposes
// ---------------------------------------------------------------------------
__global__ __launch_bounds__(256) void prep_k(
    const float* __restrict__ ht, const float* __restrict__ hc,
    __nv_bfloat16* __restrict__ Athi, __nv_bfloat16* __restrict__ Atlo,
    __nv_bfloat16* __restrict__ Achi, __nv_bfloat16* __restrict__ Aclo,
    const float* __restrict__ w_t1, const float* __restrict__ w_i1,
    __nv_bfloat16* __restrict__ Bw1hi, __nv_bfloat16* __restrict__ Bw1lo,
    __nv_bfloat16* __restrict__ Bi1hi, __nv_bfloat16* __restrict__ Bi1lo,
    const float* __restrict__ w_t2, __half* __restrict__ Bw2)
{
    const int bid = blockIdx.x;
    const int tid = threadIdx.x;

    if (bid < SPGRID) {
        if (bid == 0 && tid < 16) g_ctr[tid] = 0;
        long n1 = (long)MTXT * DD, n2 = (long)MPROJ * DD;
        long i = (long)bid * 256 + tid;
        const float* in; __nv_bfloat16 *hi, *lo;
        if (i < n1) { in = ht; hi = Athi; lo = Atlo; }
        else if (i < n1 + n2) { i -= n1; in = hc; hi = Achi; lo = Aclo; }
        else return;
        float x = in[i];
        __nv_bfloat16 h = __float2bfloat16(x);
        hi[i] = h;
        lo[i] = __float2bfloat16(x - __bfloat162float(h));

    } else if (bid < SPGRID + TW1GRID) {
        const int bt = bid - SPGRID;
        const int z  = bt / 288;
        const int r  = bt % 288;
        const int k0 = (r / 24) * 64;
        const int n0 = (r % 24) * 32;
        const float* in; __nv_bfloat16 *hi, *lo;
        if (z == 0) { in = w_t1; hi = Bw1hi; lo = Bw1lo; }
        else {
            in = w_i1 + (long)(z - 1) * DD * HH;
            hi = Bi1hi + (long)(z - 1) * HH * DD;
            lo = Bi1lo + (long)(z - 1) * HH * DD;
        }
        __shared__ float t1[64][33];
        const int x = tid & 31, y0 = tid >> 5;
#pragma unroll
        for (int i = 0; i < 8; i++) {
            int y = y0 + i * 8;
            t1[y][x] = in[(long)(k0 + y) * HH + n0 + x];
        }
        __syncthreads();
        const int lane = tid & 31, wr = tid >> 5;
#pragma unroll
        for (int i = 0; i < 4; i++) {
            int n = wr + i * 8;
            if (n >= 32) break;
            float v0 = t1[2 * lane][n], v1 = t1[2 * lane + 1][n];
            __nv_bfloat162 h2, l2;
            h2.x = __float2bfloat16(v0);
            h2.y = __float2bfloat16(v1);
            l2.x = __float2bfloat16(v0 - __bfloat162float(h2.x));
            l2.y = __float2bfloat16(v1 - __bfloat162float(h2.y));
            long o = (long)(n0 + n) * DD + k0 + 2 * lane;
            *(__nv_bfloat162*)(hi + o) = h2;
            *(__nv_bfloat162*)(lo + o) = l2;
        }

    } else {
        const int bt = bid - (SPGRID + TW1GRID);
        const int k0 = (bt / 960) * 64;
        const int n0 = (bt % 960) * 32;
        __shared__ float t2[64][33];
        const int x = tid & 31, y0 = tid >> 5;
#pragma unroll
        for (int i = 0; i < 8; i++) {
            int y = y0 + i * 8;
            int n = n0 + x;
            t2[y][x] = (n < VV) ? w_t2[(long)(k0 + y) * VV + n] : 0.f;
        }
        __syncthreads();
        const int lane = tid & 31, wr = tid >> 5;
#pragma unroll
        for (int i = 0; i < 4; i++) {
            int n = wr + i * 8;
            __half2 h2;
            h2.x = __float2half_rn(t2[2 * lane][n]);
            h2.y = __float2half_rn(t2[2 * lane + 1][n]);
            *(__half2*)(Bw2 + (long)(n0 + n) * DD + k0 + 2 * lane) = h2;
        }
    }
}

// ---------------------------------------------------------------------------
// IoU combine + mask (fp16 proj reads, 192-thr blocks)
// ---------------------------------------------------------------------------
__global__ __launch_bounds__(192) void iou_mask_k(
    const __half* __restrict__ P, const float* __restrict__ w2,
    const float* __restrict__ b2, float* __restrict__ out)
{
    const int idx = blockIdx.x;
    const int e = idx % 33;
    const int s = (idx / 33) % 32;
    const int b = idx / (33 * 32);
    const int c = (s + e) >> 1;
    const int t = threadIdx.x;

    if (t == 100 && idx < 32 * 33) {
        int i = idx / 33, j = idx % 33;
        float v = 0.f;
        int hi = (i + 17 < 33) ? (i + 17) : 33;
        if (j >= i + 1 && j < hi) v = 1.f;
        if (i < 16 && (i & 1) == 0 && j >= 18 + i && ((j - 18 - i) & 1) == 0) v = 1.f;
        out[OUT_MASK_BASE + idx] = v;
    }

    const long CS = (long)MPROJP * HH;
    // each thread handles 4 h-values: 2 half2 loads per operand
    const __half2* ps = (const __half2*)(P + (long)(b * 33 + s) * HH) + 2 * t;
    const __half2* pc = (const __half2*)(P + CS + (long)(b * 33 + c) * HH) + 2 * t;
    const __half2* pe = (const __half2*)(P + 2 * CS + (long)(b * 33 + e) * HH) + 2 * t;
    const float4* wv = (const float4*)(w2) + t * 3;

    float2 a0 = __half22float2(ps[0]), a1 = __half22float2(ps[1]);
    float2 b0 = __half22float2(pc[0]), b1 = __half22float2(pc[1]);
    float2 c0 = __half22float2(pe[0]), c1 = __half22float2(pe[1]);
    float v0 = fmaxf(a0.x + b0.x + c0.x, 0.f);
    float v1 = fmaxf(a0.y + b0.y + c0.y, 0.f);
    float v2 = fmaxf(a1.x + b1.x + c1.x, 0.f);
    float v3 = fmaxf(a1.y + b1.y + c1.y, 0.f);
    float4 w0 = wv[0], w1 = wv[1], w2v = wv[2];
    float k0 = v0 * w0.x + v1 * w0.w + v2 * w1.z + v3 * w2v.y;
    float k1 = v0 * w0.y + v1 * w1.x + v2 * w1.w + v3 * w2v.z;
    float k2 = v0 * w0.z + v1 * w1.y + v2 * w2v.x + v3 * w2v.w;

#pragma unroll
    for (int off = 16; off; off >>= 1) {
        k0 += __shfl_xor_sync(0xFFFFFFFFu, k0, off);
        k1 += __shfl_xor_sync(0xFFFFFFFFu, k1, off);
        k2 += __shfl_xor_sync(0xFFFFFFFFu, k2, off);
    }
    __shared__ float red[3][6];
    const int lane = t & 31, w = t >> 5;
    if (lane == 0) { red[0][w] = k0; red[1][w] = k1; red[2][w] = k2; }
    __syncthreads();
    if (t == 0) {
        float r0 = __ldg(b2 + 0), r1 = __ldg(b2 + 1), r2 = __ldg(b2 + 2);
#pragma unroll
        for (int i = 0; i < 6; i++) { r0 += red[0][i]; r1 += red[1][i]; r2 += red[2][i]; }
        long base = OUT_IOU_BASE + ((long)b * 3) * (32 * 33) + (long)s * 33 + e;
        out[base + 0 * 32 * 33] = r0;
        out[base + 1 * 32 * 33] = r1;
        out[base + 2 * 32 * 33] = r2;
    }
}

// ---------------------------------------------------------------------------
extern "C" void kernel_launch(void* const* d_in, const int* in_sizes, int n_in,
                              void* d_out, int out_size)
{
    const float* ht   = (const float*)d_in[0];
    const float* hc   = (const float*)d_in[1];
    const float* w_t1 = (const float*)d_in[2];
    const float* b_t1 = (const float*)d_in[3];
    const float* w_t2 = (const float*)d_in[4];
    const float* b_t2 = (const float*)d_in[5];
    const float* w_i1 = (const float*)d_in[6];
    const float* b_i1 = (const float*)d_in[7];
    const float* w_i2 = (const float*)d_in[8];
    const float* b_i2 = (const float*)d_in[9];
    float* out = (float*)d_out;

    __half* proj; cudaGetSymbolAddress((void**)&proj, g_proj);
    __nv_bfloat16 *Athi, *Atlo, *Achi, *Aclo;
    __nv_bfloat16 *Bw1hi, *Bw1lo, *Bi1hi, *Bi1lo;
    __half *H1hi, *Bw2hi;
    cudaGetSymbolAddress((void**)&Athi, g_Athi);
    cudaGetSymbolAddress((void**)&Atlo, g_Atlo);
    cudaGetSymbolAddress((void**)&Achi, g_Achi);
    cudaGetSymbolAddress((void**)&Aclo, g_Aclo);
    cudaGetSymbolAddress((void**)&H1hi, g_H1hi);
    cudaGetSymbolAddress((void**)&Bw1hi, g_Bw1hi);
    cudaGetSymbolAddress((void**)&Bw1lo, g_Bw1lo);
    cudaGetSymbolAddress((void**)&Bi1hi, g_Bi1hi);
    cudaGetSymbolAddress((void**)&Bi1lo, g_Bi1lo);
    cudaGetSymbolAddress((void**)&Bw2hi, g_Bw2hi);

    cudaFuncSetAttribute(mega_gemm, cudaFuncAttributeMaxDynamicSharedMemorySize, 147456);

    // unified prep (coalesced transposes)
    prep_k<<<SPGRID + TW1GRID + TW2GRID, 256>>>(
        ht, hc, Athi, Atlo, Achi, Aclo,
        w_t1, w_i1, Bw1hi, Bw1lo, Bi1hi, Bi1lo,
        w_t2, Bw2hi);
    // mega GEMM: gemm1 + projections + vocab (per-row-block counters)
    mega_gemm<<<G1GRID + PRGRID + VOGRID, 256, 147456>>>(
        Athi, Atlo, Bw1hi, Bw1lo, b_t1, H1hi,
        Achi, Aclo, Bi1hi, Bi1lo, b_i1, proj,
        Bw2hi, b_t2, out);
    // IoU combine + mask
    iou_mask_k<<<BB * TT * (TT + 1), 192>>>(proj, w_i2, b_i2, out);
}

// round 13
// speedup vs baseline: 1.7443x; 1.0876x over previous
#include <cuda_runtime.h>
#include <cuda_bf16.h>
#include <cuda_fp16.h>
#include <cstdint>

// Problem shapes
#define BB 32
#define LL 48
#define DD 768
#define TT 32
#define VV 30522
#define HH 768
#define NPAD 30720   // 120 * 256
#define MPROJ 1056   // 32*33
#define MPROJP 1152
#define MTXT 1536

#define OUT_TEXT_ELEMS ((long)BB * LL * VV)
#define OUT_IOU_ELEMS  ((long)BB * 3 * TT * (TT+1))
#define OUT_IOU_BASE   (OUT_TEXT_ELEMS)
#define OUT_MASK_BASE  (OUT_TEXT_ELEMS + OUT_IOU_ELEMS)

// mega-kernel block ranges (all fp16 1-term, tile 128x256)
#define G1GRID 36    // gemm1: 12 rowtiles x 3 coltiles
#define PRGRID 81    // proj: 3 z x 9 rowtiles x 3 coltiles
#define VOGRID 1440  // vocab: 12 rowtiles x 120 coltiles

// prep-kernel block ranges
#define SPGRID 7776    // elementwise fp32->fp16 of ht+hc
#define TW1GRID 1152   // w_t1 + w_i1 transpose: 4 z * (12 ktiles * 24 ntiles)
#define TW2GRID 11520  // w_t2 transpose: 12 ktiles * 960 ntiles

// Scratch (device globals; no allocations allowed)
__device__ int    g_ctr[16];   // [0..11]: per-row-block gemm1 tile count (target 3)
__device__ __half g_proj[3L * MPROJP * HH];
__device__ __half g_At16[(long)MTXT * DD];
__device__ __half g_Ac16[(long)MPROJ * DD];
__device__ __half g_H1hi[(long)MTXT * HH];
__device__ __half g_Bw1h[(long)HH * DD];
__device__ __half g_Bi1h[3L * HH * DD];
__device__ __half g_Bw2hi[(long)NPAD * DD];

// ---------------------------------------------------------------------------
// helpers
// ---------------------------------------------------------------------------
__device__ __forceinline__ uint32_t smem_u32(const void* p) {
    uint32_t a;
    asm("{ .reg .u64 t; cvta.to.shared.u64 t, %1; cvt.u32.u64 %0, t; }" : "=r"(a) : "l"(p));
    return a;
}
__device__ __forceinline__ void cp_async16(uint32_t saddr, const void* gptr) {
    asm volatile("cp.async.cg.shared.global [%0], [%1], 16;" :: "r"(saddr), "l"(gptr));
}
__device__ __forceinline__ void cp_async16z(uint32_t saddr, const void* gptr, bool pred) {
    int sz = pred ? 16 : 0;
    asm volatile("cp.async.cg.shared.global [%0], [%1], 16, %2;"
                 :: "r"(saddr), "l"(gptr), "r"(sz));
}
#define CP_COMMIT()  asm volatile("cp.async.commit_group;" ::: "memory")
#define CP_WAIT2()   asm volatile("cp.async.wait_group 2;" ::: "memory")
#define CP_WAIT1()   asm volatile("cp.async.wait_group 1;" ::: "memory")
#define CP_WAIT0()   asm volatile("cp.async.wait_group 0;" ::: "memory")

#define SWZ(o) ((o) ^ (((o) >> 3) & 0x70))

__device__ __forceinline__ void ldsm_x4(uint32_t addr, uint32_t& r0, uint32_t& r1,
                                        uint32_t& r2, uint32_t& r3) {
    asm volatile("ldmatrix.sync.aligned.m8n8.x4.shared.b16 {%0,%1,%2,%3}, [%4];"
                 : "=r"(r0), "=r"(r1), "=r"(r2), "=r"(r3) : "r"(addr));
}
__device__ __forceinline__ void mma_f16(float* d, const uint32_t* a, const uint32_t* b) {
    asm volatile(
        "mma.sync.aligned.m16n8k16.row.col.f32.f16.f16.f32 "
        "{%0,%1,%2,%3}, {%4,%5,%6,%7}, {%8,%9}, {%0,%1,%2,%3};"
        : "+f"(d[0]), "+f"(d[1]), "+f"(d[2]), "+f"(d[3])
        : "r"(a[0]), "r"(a[1]), "r"(a[2]), "r"(a[3]), "r"(b[0]), "r"(b[1]));
}

// producer/consumer sync
__device__ __forceinline__ void signal_ctr(int* c) {
    __syncthreads();
    if (threadIdx.x == 0) { __threadfence(); atomicAdd(c, 1); }
}
__device__ __forceinline__ void wait_ctr(int* c, int target) {
    if (threadIdx.x == 0) {
        volatile int* vc = c;
        while (*vc < target) __nanosleep(64);
    }
    __syncthreads();
    __threadfence();
}

// ---------------------------------------------------------------------------
// fp16 1-term mainloop: tile 128x256, K=768 (12 chunks of 64), 3-stage 48KB.
// 8 warps = 2(M) x 4(N), warp tile 64x64. Accumulates into acc[4][8][4].
// ---------------------------------------------------------------------------
#define KCHUNK 12

__device__ __forceinline__ void mainloop_f16(
    uint32_t sbase, int tid, int wid, int lane, int row0, int col0, int Mclip,
    const __half* __restrict__ A, const __half* __restrict__ B,
    float acc[4][8][4])
{
    const int wm = (wid & 1) * 64;
    const int wn = (wid >> 1) * 64;
    const int a_m  = lane & 15;
    const int a_kb = (lane >> 4) << 4;
    const int b_n  = (lane & 7) + ((lane >> 4) << 3);
    const int b_kb = ((lane >> 3) & 1) << 4;

#define LOAD_CHUNKF(KC)                                                         \
    {                                                                           \
        int kk = (KC) * 64;                                                     \
        uint32_t st = sbase + ((KC) % 3) * 49152;                               \
        _Pragma("unroll")                                                       \
        for (int i = 0; i < 4; i++) {                                           \
            int idx = tid + (i << 8);                                           \
            int m = idx >> 3, j = idx & 7;                                      \
            int grow = row0 + m;                                                \
            bool pa = grow < Mclip;                                             \
            cp_async16z(st + SWZ(m * 128 + j * 16),                             \
                        A + (size_t)(pa ? grow : 0) * DD + kk + j * 8, pa);     \
        }                                                                       \
        _Pragma("unroll")                                                       \
        for (int i = 0; i < 8; i++) {                                           \
            int idx = tid + (i << 8);                                           \
            int m = idx >> 3, j = idx & 7;                                      \
            cp_async16(st + 16384 + SWZ(m * 128 + j * 16),                      \
                       B + (size_t)(col0 + m) * DD + kk + j * 8);               \
        }                                                                       \
        CP_COMMIT();                                                            \
    }

    LOAD_CHUNKF(0);
    LOAD_CHUNKF(1);
    LOAD_CHUNKF(2);

    for (int kc = 0; kc < KCHUNK; kc++) {
        if (kc < KCHUNK - 2)       { CP_WAIT2(); }
        else if (kc == KCHUNK - 2) { CP_WAIT1(); }
        else                       { CP_WAIT0(); }
        __syncthreads();
        const uint32_t sA = sbase + (kc % 3) * 49152;
        const uint32_t sB = sA + 16384;

#pragma unroll
        for (int k16 = 0; k16 < 4; k16++) {
            const int kb = k16 * 32;
            uint32_t a[4][4], b[4][4];
#pragma unroll
            for (int mf = 0; mf < 4; mf++)
                ldsm_x4(sA + SWZ((wm + mf * 16 + a_m) * 128 + kb + a_kb),
                        a[mf][0], a[mf][1], a[mf][2], a[mf][3]);
#pragma unroll
            for (int np = 0; np < 4; np++)
                ldsm_x4(sB + SWZ((wn + np * 16 + b_n) * 128 + kb + b_kb),
                        b[np][0], b[np][1], b[np][2], b[np][3]);
#pragma unroll
            for (int mf = 0; mf < 4; mf++) {
#pragma unroll
                for (int nf = 0; nf < 8; nf++) {
                    uint32_t bb[2] = { b[nf >> 1][(nf & 1) * 2],
                                       b[nf >> 1][(nf & 1) * 2 + 1] };
                    mma_f16(acc[mf][nf], a[mf], bb);
                }
            }
        }
        __syncthreads();
        if (kc + 3 < KCHUNK) LOAD_CHUNKF(kc + 3);
    }
#undef LOAD_CHUNKF
}

// ---------------------------------------------------------------------------
// GEMM mega kernel: gemm1 (36) -> proj (81) -> vocab (1440).
// vocab waits per-row-block: g_ctr[rowblk] == 3.
// ---------------------------------------------------------------------------
__global__ __launch_bounds__(256) void mega_gemm(
    const __half* __restrict__ At16, const __half* __restrict__ Bw1h,
    const float* __restrict__ b_t1, __half* __restrict__ H1hi,
    const __half* __restrict__ Ac16, const __half* __restrict__ Bi1h,
    const float* __restrict__ b_i1, __half* __restrict__ proj,
    const __half* __restrict__ Bw2,
    const float* __restrict__ b_t2, float* __restrict__ out)
{
    extern __shared__ char smem[];
    const uint32_t sbase = smem_u32(smem);
    const int tid  = threadIdx.x;
    const int wid  = tid >> 5;
    const int lane = tid & 31;
    const int em = lane >> 2;
    const int en = (lane & 3) * 2;
    const int bid = blockIdx.x;
    const int wm = (wid & 1) * 64;
    const int wn = (wid >> 1) * 64;

    float acc[4][8][4];
#pragma unroll
    for (int i = 0; i < 4; i++)
#pragma unroll
        for (int j = 0; j < 8; j++)
#pragma unroll
            for (int r = 0; r < 4; r++) acc[i][j][r] = 0.f;

    if (bid < G1GRID) {
        // ===================== GEMM1: h1 -> fp16 =====================
        const int rowblk = bid / 3;
        const int row0 = rowblk * 128;
        const int col0 = (bid % 3) * 256;
        mainloop_f16(sbase, tid, wid, lane, row0, col0, MTXT, At16, Bw1h, acc);
#pragma unroll
        for (int mf = 0; mf < 4; mf++) {
#pragma unroll
            for (int half = 0; half < 2; half++) {
                int gr = row0 + wm + mf * 16 + em + half * 8;
#pragma unroll
                for (int nf = 0; nf < 8; nf++) {
                    int gc = col0 + wn + nf * 8 + en;
                    float vx = fmaxf(acc[mf][nf][half * 2]     + __ldg(b_t1 + gc), 0.f);
                    float vy = fmaxf(acc[mf][nf][half * 2 + 1] + __ldg(b_t1 + gc + 1), 0.f);
                    __half2 h;
                    h.x = __float2half_rn(vx);
                    h.y = __float2half_rn(vy);
                    *(__half2*)(H1hi + (size_t)gr * HH + gc) = h;
                }
            }
        }
        signal_ctr(&g_ctr[rowblk]);

    } else if (bid < G1GRID + PRGRID) {
        // ===================== projections (fp16 out) =====================
        const int p = bid - G1GRID;
        const int pz = p / 27;
        const int r  = p % 27;
        const int row0 = (r / 3) * 128;
        const int col0 = (r % 3) * 256;
        mainloop_f16(sbase, tid, wid, lane, row0, col0, MPROJ,
                     Ac16, Bi1h + (long)pz * HH * DD, acc);
        __half* Cf = proj + (long)pz * MPROJP * HH;
        const bool bias_on = (pz == 0);
#pragma unroll
        for (int mf = 0; mf < 4; mf++) {
#pragma unroll
            for (int half = 0; half < 2; half++) {
                int gr = row0 + wm + mf * 16 + em + half * 8;
#pragma unroll
                for (int nf = 0; nf < 8; nf++) {
                    int gc = col0 + wn + nf * 8 + en;
                    float vx = acc[mf][nf][half * 2];
                    float vy = acc[mf][nf][half * 2 + 1];
                    if (bias_on) { vx += __ldg(b_i1 + gc); vy += __ldg(b_i1 + gc + 1); }
                    __half2 h;
                    h.x = __float2half_rn(vx);
                    h.y = __float2half_rn(vy);
                    *(__half2*)(Cf + (size_t)gr * HH + gc) = h;
                }
            }
        }

    } else {
        // ===================== vocab GEMM =====================
        const int v = bid - (G1GRID + PRGRID);
        const int col0 = (v % 120) * 256;
        const int rowblk = v / 120;
        const int row0 = rowblk * 128;
        wait_ctr(&g_ctr[rowblk], 3);
        mainloop_f16(sbase, tid, wid, lane, row0, col0, MTXT, H1hi, Bw2, acc);
#pragma unroll
        for (int mf = 0; mf < 4; mf++) {
#pragma unroll
            for (int half = 0; half < 2; half++) {
                int gr = row0 + wm + mf * 16 + em + half * 8;
                float* orow = out + (size_t)gr * VV;
#pragma unroll
                for (int nf = 0; nf < 8; nf++) {
                    int gc = col0 + wn + nf * 8 + en;
                    if (gc + 1 < VV) {
                        float2 vv = { acc[mf][nf][half * 2]     + __ldg(b_t2 + gc),
                                      acc[mf][nf][half * 2 + 1] + __ldg(b_t2 + gc + 1) };
                        *(float2*)(orow + gc) = vv;
                    } else if (gc < VV) {
                        orow[gc] = acc[mf][nf][half * 2] + __ldg(b_t2 + gc);
                    }
                }
            }
        }
    }
}

// ---------------------------------------------------------------------------
// Unified prep kernel (256 threads), coalesced transposes, all fp16:
//   [0, SPGRID)                : fp32->fp16 of ht, hc (+ctr reset)
//   [SPGRID, +TW1GRID)         : transpose w_t1/w_i1 -> fp16, 64k x 32n tiles
//   [SPGRID+TW1GRID, +TW2GRID) : transpose w_t2 -> fp16, 64k x 32n tiles
// ---------------------------------------------------------------------------
__global__ __launch_bounds__(256) void prep_k(
    const float* __restrict__ ht, const float* __restrict__ hc,
    __half* __restrict__ At16, __half* __restrict__ Ac16,
    const float* __restrict__ w_t1, const float* __restrict__ w_i1,
    __half* __restrict__ Bw1h, __half* __restrict__ Bi1h,
    const float* __restrict__ w_t2, __half* __restrict__ Bw2)
{
    const int bid = blockIdx.x;
    const int tid = threadIdx.x;

    if (bid < SPGRID) {
        if (bid == 0 && tid < 16) g_ctr[tid] = 0;
        long n1 = (long)MTXT * DD, n2 = (long)MPROJ * DD;
        long i = (long)bid * 256 + tid;
        if (i < n1) At16[i] = __float2half_rn(ht[i]);
        else if (i < n1 + n2) { i -= n1; Ac16[i] = __float2half_rn(hc[i]); }

    } else if (bid < SPGRID + TW1GRID) {
        const int bt = bid - SPGRID;
        const int z  = bt / 288;
        const int r  = bt % 288;
        const int k0 = (r / 24) * 64;
        const int n0 = (r % 24) * 32;
        const float* in; __half* hi;
        if (z == 0) { in = w_t1; hi = Bw1h; }
        else {
            in = w_i1 + (long)(z - 1) * DD * HH;
            hi = Bi1h + (long)(z - 1) * HH * DD;
        }
        __shared__ float t1[64][33];
        const int x = tid & 31, y0 = tid >> 5;
#pragma unroll
        for (int i = 0; i < 8; i++) {
            int y = y0 + i * 8;
            t1[y][x] = in[(long)(k0 + y) * HH + n0 + x];
        }
        __syncthreads();
        const int lane = tid & 31, wr = tid >> 5;
#pragma unroll
        for (int i = 0; i < 4; i++) {
            int n = wr + i * 8;
            __half2 h2;
            h2.x = __float2half_rn(t1[2 * lane][n]);
            h2.y = __float2half_rn(t1[2 * lane + 1][n]);
            *(__half2*)(hi + (long)(n0 + n) * DD + k0 + 2 * lane) = h2;
        }

    } else {
        const int bt = bid - (SPGRID + TW1GRID);
        const int k0 = (bt / 960) * 64;
        const int n0 = (bt % 960) * 32;
        __shared__ float t2[64][33];
        const int x = tid & 31, y0 = tid >> 5;
#pragma unroll
        for (int i = 0; i < 8; i++) {
            int y = y0 + i * 8;
            int n = n0 + x;
            t2[y][x] = (n < VV) ? w_t2[(long)(k0 + y) * VV + n] : 0.f;
        }
        __syncthreads();
        const int lane = tid & 31, wr = tid >> 5;
#pragma unroll
        for (int i = 0; i < 4; i++) {
            int n = wr + i * 8;
            __half2 h2;
            h2.x = __float2half_rn(t2[2 * lane][n]);
            h2.y = __float2half_rn(t2[2 * lane + 1][n]);
            *(__half2*)(Bw2 + (long)(n0 + n) * DD + k0 + 2 * lane) = h2;
        }
    }
}

// ---------------------------------------------------------------------------
// IoU combine + mask (fp16 proj reads, 192-thr blocks)
// ---------------------------------------------------------------------------
__global__ __launch_bounds__(192) void iou_mask_k(
    const __half* __restrict__ P, const float* __restrict__ w2,
    const float* __restrict__ b2, float* __restrict__ out)
{
    const int idx = blockIdx.x;
    const int e = idx % 33;
    const int s = (idx / 33) % 32;
    const int b = idx / (33 * 32);
    const int c = (s + e) >> 1;
    const int t = threadIdx.x;

    if (t == 100 && idx < 32 * 33) {
        int i = idx / 33, j = idx % 33;
        float v = 0.f;
        int hi = (i + 17 < 33) ? (i + 17) : 33;
        if (j >= i + 1 && j < hi) v = 1.f;
        if (i < 16 && (i & 1) == 0 && j >= 18 + i && ((j - 18 - i) & 1) == 0) v = 1.f;
        out[OUT_MASK_BASE + idx] = v;
    }

    const long CS = (long)MPROJP * HH;
    const __half2* ps = (const __half2*)(P + (long)(b * 33 + s) * HH) + 2 * t;
    const __half2* pc = (const __half2*)(P + CS + (long)(b * 33 + c) * HH) + 2 * t;
    const __half2* pe = (const __half2*)(P + 2 * CS + (long)(b * 33 + e) * HH) + 2 * t;
    const float4* wv = (const float4*)(w2) + t * 3;

    float2 a0 = __half22float2(ps[0]), a1 = __half22float2(ps[1]);
    float2 b0 = __half22float2(pc[0]), b1 = __half22float2(pc[1]);
    float2 c0 = __half22float2(pe[0]), c1 = __half22float2(pe[1]);
    float v0 = fmaxf(a0.x + b0.x + c0.x, 0.f);
    float v1 = fmaxf(a0.y + b0.y + c0.y, 0.f);
    float v2 = fmaxf(a1.x + b1.x + c1.x, 0.f);
    float v3 = fmaxf(a1.y + b1.y + c1.y, 0.f);
    float4 w0 = wv[0], w1 = wv[1], w2v = wv[2];
    float k0 = v0 * w0.x + v1 * w0.w + v2 * w1.z + v3 * w2v.y;
    float k1 = v0 * w0.y + v1 * w1.x + v2 * w1.w + v3 * w2v.z;
    float k2 = v0 * w0.z + v1 * w1.y + v2 * w2v.x + v3 * w2v.w;

#pragma unroll
    for (int off = 16; off; off >>= 1) {
        k0 += __shfl_xor_sync(0xFFFFFFFFu, k0, off);
        k1 += __shfl_xor_sync(0xFFFFFFFFu, k1, off);
        k2 += __shfl_xor_sync(0xFFFFFFFFu, k2, off);
    }
    __shared__ float red[3][6];
    const int lane = t & 31, w = t >> 5;
    if (lane == 0) { red[0][w] = k0; red[1][w] = k1; red[2][w] = k2; }
    __syncthreads();
    if (t == 0) {
        float r0 = __ldg(b2 + 0), r1 = __ldg(b2 + 1), r2 = __ldg(b2 + 2);
#pragma unroll
        for (int i = 0; i < 6; i++) { r0 += red[0][i]; r1 += red[1][i]; r2 += red[2][i]; }
        long base = OUT_IOU_BASE + ((long)b * 3) * (32 * 33) + (long)s * 33 + e;
        out[base + 0 * 32 * 33] = r0;
        out[base + 1 * 32 * 33] = r1;
        out[base + 2 * 32 * 33] = r2;
    }
}

// ---------------------------------------------------------------------------
extern "C" void kernel_launch(void* const* d_in, const int* in_sizes, int n_in,
                              void* d_out, int out_size)
{
    const float* ht   = (const float*)d_in[0];
    const float* hc   = (const float*)d_in[1];
    const float* w_t1 = (const float*)d_in[2];
    const float* b_t1 = (const float*)d_in[3];
    const float* w_t2 = (const float*)d_in[4];
    const float* b_t2 = (const float*)d_in[5];
    const float* w_i1 = (const float*)d_in[6];
    const float* b_i1 = (const float*)d_in[7];
    const float* w_i2 = (const float*)d_in[8];
    const float* b_i2 = (const float*)d_in[9];
    float* out = (float*)d_out;

    __half *proj, *At16, *Ac16, *H1hi, *Bw1h, *Bi1h, *Bw2hi;
    cudaGetSymbolAddress((void**)&proj, g_proj);
    cudaGetSymbolAddress((void**)&At16, g_At16);
    cudaGetSymbolAddress((void**)&Ac16, g_Ac16);
    cudaGetSymbolAddress((void**)&H1hi, g_H1hi);
    cudaGetSymbolAddress((void**)&Bw1h, g_Bw1h);
    cudaGetSymbolAddress((void**)&Bi1h, g_Bi1h);
    cudaGetSymbolAddress((void**)&Bw2hi, g_Bw2hi);

    cudaFuncSetAttribute(mega_gemm, cudaFuncAttributeMaxDynamicSharedMemorySize, 147456);

    // unified prep (all fp16)
    prep_k<<<SPGRID + TW1GRID + TW2GRID, 256>>>(
        ht, hc, At16, Ac16, w_t1, w_i1, Bw1h, Bi1h, w_t2, Bw2hi);
    // mega GEMM: gemm1 + projections + vocab (all fp16 1-term, 128x256 tiles)
    mega_gemm<<<G1GRID + PRGRID + VOGRID, 256, 147456>>>(
        At16, Bw1h, b_t1, H1hi,
        Ac16, Bi1h, b_i1, proj,
        Bw2hi, b_t2, out);
    // IoU combine + mask
    iou_mask_k<<<BB * TT * (TT + 1), 192>>>(proj, w_i2, b_i2, out);
}